// round 8
// baseline (speedup 1.0000x reference)
#include <cuda_runtime.h>
#include <cuda_bf16.h>
#include <cstdint>

typedef unsigned long long u64;

// ============================================================================
// Multi-kernel tensor-core rewrite (mma.sync HMMA path; tcgen05 unavailable —
// harness PTX target is plain sm_100).
//  - Generic split-bf16 mma.sync GEMM: C[20480,N] = A[20480,K] @ W[K,N] (+bias)
//    3-term bf16 split (hi*hi + hi*lo + lo*hi), fp32 accumulate.
//  - Per-graph fp32 edge kernels (GATv2 logits/softmax/aggregate, CGConv edge).
//  - Head kernel (pool + MLP).
// Round 8 = round 7 resubmit after infra failure, with one bug fixed:
// gat_edge att staging now loops (256-thread block must load 512 floats).
// ============================================================================

namespace {
constexpr int NNODE = 20480;   // 2048 graphs * 10 nodes
constexpr int NG    = 2048;
constexpr int Hd    = 128;
constexpr int CDm   = 32;
}

// -------- global scratch (device globals: allowed) --------
__device__ float g_XM[NNODE*Hd];
__device__ float g_XO[NNODE*Hd];
__device__ float g_NM[NNODE*Hd];
__device__ float g_NO[NNODE*Hd];
__device__ float g_XL[NNODE*512];
__device__ float g_XR[NNODE*512];
__device__ float g_Fd[NNODE*Hd];
__device__ float g_Fs[NNODE*Hd];
__device__ float g_Sd[NNODE*Hd];
__device__ float g_Ss[NNODE*Hd];

__device__ __forceinline__ void mma16816(float* d, const uint32_t* a,
                                         uint32_t b0, uint32_t b1) {
    asm volatile(
        "mma.sync.aligned.m16n8k16.row.col.f32.bf16.bf16.f32 "
        "{%0,%1,%2,%3}, {%4,%5,%6,%7}, {%8,%9}, {%0,%1,%2,%3};"
        : "+f"(d[0]), "+f"(d[1]), "+f"(d[2]), "+f"(d[3])
        : "r"(a[0]), "r"(a[1]), "r"(a[2]), "r"(a[3]), "r"(b0), "r"(b1));
}

// ============================================================================
// Split-bf16 GEMM: C[m0:m0+128, n0:n0+128] = A[:,K] @ W[K,Ntot] (+bias)
// grid = (M/128, Ntot/128), block = 256. smem = 4 * 128 * (K+8) * 2 bytes.
// A smem: row-major [128][KP]. B smem: transposed [n][KP] (Bs[n][k]=W[k][n0+n]).
// ============================================================================
extern "C" __global__ void __launch_bounds__(256, 1)
gemm_bf16s_kernel(const float* __restrict__ A, const float* __restrict__ W,
                  const float* __restrict__ bias, float* __restrict__ C,
                  int K, int Ntot)
{
    extern __shared__ __align__(16) char smem_raw[];
    __nv_bfloat16* s = (__nv_bfloat16*)smem_raw;
    const int KP = K + 8;
    __nv_bfloat16* Ah = s;
    __nv_bfloat16* Al = s + 128*KP;
    __nv_bfloat16* Bh = s + 2*128*KP;
    __nv_bfloat16* Bl = s + 3*128*KP;

    const int t  = threadIdx.x;
    const int m0 = blockIdx.x * 128;
    const int n0 = blockIdx.y * 128;

    // ---- stage A tile [128, K] (coalesced over k) ----
    for (int idx = t; idx < 128*K; idx += 256) {
        const int r = idx / K, k = idx - r*K;
        const float a = A[(size_t)(m0 + r)*K + k];
        const __nv_bfloat16 hi = __float2bfloat16(a);
        const __nv_bfloat16 lo = __float2bfloat16(a - __bfloat162float(hi));
        Ah[r*KP + k] = hi;
        Al[r*KP + k] = lo;
    }
    // ---- stage B transposed: Bs[n][k] = W[k][n0+n] (coalesced over n) ----
    for (int idx = t; idx < 128*K; idx += 256) {
        const int k = idx >> 7, n = idx & 127;
        const float w = W[(size_t)k*Ntot + n0 + n];
        const __nv_bfloat16 hi = __float2bfloat16(w);
        const __nv_bfloat16 lo = __float2bfloat16(w - __bfloat162float(hi));
        Bh[n*KP + k] = hi;
        Bl[n*KP + k] = lo;
    }
    __syncthreads();

    const int wid = t >> 5, lane = t & 31;
    const int wm = wid & 3, wn = wid >> 2;     // 4 (M) x 2 (N) warps
    const int gID = lane >> 2, tig = lane & 3;

    float acc[2][8][4];
#pragma unroll
    for (int mt = 0; mt < 2; mt++)
#pragma unroll
        for (int nt = 0; nt < 8; nt++)
#pragma unroll
            for (int q = 0; q < 4; q++) acc[mt][nt][q] = 0.f;

#pragma unroll 1
    for (int term = 0; term < 3; term++) {
        const __nv_bfloat16* As = (term == 2) ? Al : Ah;
        const __nv_bfloat16* Bs = (term == 1) ? Bl : Bh;
#pragma unroll 1
        for (int k0 = 0; k0 < K; k0 += 16) {
            uint32_t afr[2][4];
#pragma unroll
            for (int mt = 0; mt < 2; mt++) {
                const int row = wm*32 + mt*16 + gID;
                const __nv_bfloat16* ap = As + row*KP + k0 + 2*tig;
                afr[mt][0] = *(const uint32_t*)ap;            // (r,   k0+2t)
                afr[mt][1] = *(const uint32_t*)(ap + 8*KP);   // (r+8, k0+2t)
                afr[mt][2] = *(const uint32_t*)(ap + 8);      // (r,   k0+2t+8)
                afr[mt][3] = *(const uint32_t*)(ap + 8*KP + 8);
            }
#pragma unroll
            for (int nt = 0; nt < 8; nt++) {
                const int col = wn*64 + nt*8 + gID;
                const __nv_bfloat16* bp = Bs + col*KP + k0 + 2*tig;
                const uint32_t b0 = *(const uint32_t*)bp;        // (k0+2t,   n)
                const uint32_t b1 = *(const uint32_t*)(bp + 8);  // (k0+2t+8, n)
                mma16816(acc[0][nt], afr[0], b0, b1);
                mma16816(acc[1][nt], afr[1], b0, b1);
            }
        }
    }

    // ---- epilogue: c0,c1 -> (row, 2t..2t+1); c2,c3 -> (row+8, ...) ----
#pragma unroll
    for (int mt = 0; mt < 2; mt++) {
        const int row = m0 + wm*32 + mt*16 + gID;
#pragma unroll
        for (int nt = 0; nt < 8; nt++) {
            const int col = n0 + wn*64 + nt*8 + 2*tig;
            float2 v0 = make_float2(acc[mt][nt][0], acc[mt][nt][1]);
            float2 v1 = make_float2(acc[mt][nt][2], acc[mt][nt][3]);
            if (bias) {
                const float2 bb = *(const float2*)&bias[col];
                v0.x += bb.x; v0.y += bb.y;
                v1.x += bb.x; v1.y += bb.y;
            }
            *(float2*)&C[(size_t)row*Ntot + col]       = v0;
            *(float2*)&C[(size_t)(row + 8)*Ntot + col] = v1;
        }
    }
}

// ============================================================================
// GATv2 edge kernel: per graph — logits, softmax over src, aggregate, +bias.
// XL/XR: [NNODE, 512] (col = h*128 + c). OUT: [NNODE, 128].
// ============================================================================
extern "C" __global__ void __launch_bounds__(256)
gat_edge_kernel(const float* __restrict__ XL, const float* __restrict__ XR,
                const float* __restrict__ att, const float* __restrict__ bias,
                float* __restrict__ OUT, int accum)
{
    __shared__ float sXL[10*512], sXR[10*512], sLog[40*16], sAtt[512];
    const int g = blockIdx.x, t = threadIdx.x;
    const int wid = t >> 5, lane = t & 31;
    const size_t base = (size_t)g * 5120;

    for (int idx = t; idx < 5120; idx += 256) {
        sXL[idx] = XL[base + idx];
        sXR[idx] = XR[base + idx];
    }
    for (int idx = t; idx < 512; idx += 256) sAtt[idx] = att[idx];
    __syncthreads();

    // logits: warp per (h,j); leaky(e) = 0.6e + 0.4|e|
#pragma unroll 1
    for (int pp = 0; pp < 5; pp++) {
        const int p = wid + pp * 8;          // 0..39 = h*10+j
        const int h = p / 10, j = p % 10;
        const float4 xr = *(const float4*)&sXR[j*512 + h*128 + lane*4];
        const float4 at = *(const float4*)&sAtt[h*128 + lane*4];
#pragma unroll
        for (int i = 0; i < 10; i++) {
            const float4 xl = *(const float4*)&sXL[i*512 + h*128 + lane*4];
            float e, s;
            e = xl.x + xr.x; s = at.x * fmaf(e, 0.6f, 0.4f*fabsf(e));
            e = xl.y + xr.y; s = fmaf(at.y, fmaf(e, 0.6f, 0.4f*fabsf(e)), s);
            e = xl.z + xr.z; s = fmaf(at.z, fmaf(e, 0.6f, 0.4f*fabsf(e)), s);
            e = xl.w + xr.w; s = fmaf(at.w, fmaf(e, 0.6f, 0.4f*fabsf(e)), s);
#pragma unroll
            for (int o = 16; o > 0; o >>= 1) s += __shfl_xor_sync(0xffffffffu, s, o);
            if (lane == 0) sLog[p*16 + i] = s;
        }
    }
    __syncthreads();

    // softmax over i per (h,j)
    if (t < 40) {
        float* lg = sLog + t*16;
        float m = lg[0];
#pragma unroll
        for (int i = 1; i < 10; i++) m = fmaxf(m, lg[i]);
        float a[10]; float sum = 0.f;
#pragma unroll
        for (int i = 0; i < 10; i++) { a[i] = __expf(lg[i] - m); sum += a[i]; }
        const float inv = __fdividef(1.f, sum);
#pragma unroll
        for (int i = 0; i < 10; i++) lg[i] = a[i] * inv;
    }
    __syncthreads();

    // aggregate: out[j,c] = bias[c] + 0.25 * sum_h sum_i alpha * XL[i,h,c]
    {
        const int c = t & 127, rh = t >> 7;
        float accj[5] = {0.f, 0.f, 0.f, 0.f, 0.f};
#pragma unroll
        for (int h = 0; h < 4; h++) {
            float xlh[10];
#pragma unroll
            for (int i = 0; i < 10; i++) xlh[i] = sXL[i*512 + h*128 + c];
#pragma unroll
            for (int jj = 0; jj < 5; jj++) {
                const float* al = sLog + (h*10 + rh*5 + jj)*16;
                float v = accj[jj];
#pragma unroll
                for (int i = 0; i < 10; i++) v = fmaf(al[i], xlh[i], v);
                accj[jj] = v;
            }
        }
        const float bv = bias[c];
#pragma unroll
        for (int jj = 0; jj < 5; jj++) {
            const int j = rh*5 + jj;
            const size_t idx = (size_t)(g*10 + j)*128 + c;
            const float v = accj[jj]*0.25f + bv;
            OUT[idx] = accum ? (OUT[idx] + v) : v;
        }
    }
}

// ============================================================================
// CGConv edge kernel: out_i = x_dst_i + sum_j sigmoid(Fd_i+Fs_j)*softplus(Sd_i+Ss_j)
// ============================================================================
extern "C" __global__ void __launch_bounds__(256)
cg_edge_kernel(const float* __restrict__ Fd, const float* __restrict__ Fs,
               const float* __restrict__ Sd, const float* __restrict__ Ss,
               const float* __restrict__ Xd, float* __restrict__ OUT, int accum)
{
    __shared__ float sFd[1280], sFs[1280], sSd[1280], sSs[1280], sXd[1280];
    const int g = blockIdx.x, t = threadIdx.x;
    const size_t base = (size_t)g * 1280;
    for (int idx = t; idx < 1280; idx += 256) {
        sFd[idx] = Fd[base + idx]; sFs[idx] = Fs[base + idx];
        sSd[idx] = Sd[base + idx]; sSs[idx] = Ss[base + idx];
        sXd[idx] = Xd[base + idx];
    }
    __syncthreads();
    const int c = t & 127, rh = t >> 7;
#pragma unroll
    for (int jj = 0; jj < 5; jj++) {
        const int i = rh*5 + jj;
        const float fd = sFd[i*128 + c];
        const float sd = sSd[i*128 + c];
        float acc = sXd[i*128 + c];
#pragma unroll
        for (int j = 0; j < 10; j++) {
            const float f = fd + sFs[j*128 + c];
            const float s = sd + sSs[j*128 + c];
            const float sig = __fdividef(1.f, 1.f + __expf(-f));
            const float sp  = fmaxf(s, 0.f) + __logf(1.f + __expf(-fabsf(s)));
            acc = fmaf(sig, sp, acc);
        }
        const size_t idx = base + i*128 + c;
        OUT[idx] = accum ? (OUT[idx] + acc) : acc;
    }
}

// ============================================================================
// Head: per graph — mean pool both types, MLP, write scalar
// ============================================================================
extern "C" __global__ void __launch_bounds__(128)
head_kernel(const float* __restrict__ XM, const float* __restrict__ XO,
            const float* __restrict__ W1, const float* __restrict__ b1,
            const float* __restrict__ W2, const float* __restrict__ b2,
            float* __restrict__ out)
{
    __shared__ float pool[256], red[128];
    const int g = blockIdx.x, t = threadIdx.x;
    {
        float pm = 0.f, po = 0.f;
#pragma unroll
        for (int r = 0; r < 10; r++) {
            pm += XM[(size_t)(g*10 + r)*128 + t];
            po += XO[(size_t)(g*10 + r)*128 + t];
        }
        pool[t] = pm * 0.1f;
        pool[128 + t] = po * 0.1f;
    }
    __syncthreads();
    {
        float a = 0.f;
#pragma unroll 4
        for (int k = 0; k < 256; k++) a = fmaf(pool[k], W1[k*128 + t], a);
        a += b1[t];
        a = (a >= 0.f) ? a : 128.f * a;     // LeakyReLU slope = final_dim
        red[t] = a * W2[t];
    }
    __syncthreads();
    if (t < 32) {
        float v = red[t] + red[t+32] + red[t+64] + red[t+96];
#pragma unroll
        for (int o = 16; o > 0; o >>= 1) v += __shfl_xor_sync(0xffffffffu, v, o);
        if (t == 0) out[g] = v + b2[0];
    }
}

// ============================================================================
// Host launcher
// ============================================================================
extern "C" void kernel_launch(void* const* d_in, const int* in_sizes, int n_in,
                              void* d_out, int out_size)
{
    const float* x_my   = (const float*)d_in[0];
    const float* x_opp  = (const float*)d_in[1];
    const float* W_enc  = (const float*)d_in[2];
    const float* b_enc  = (const float*)d_in[3];
    const float* gb_Wl  = (const float*)d_in[4];
    const float* gb_Wr  = (const float*)d_in[5];
    const float* gb_att = (const float*)d_in[6];
    const float* gb_b   = (const float*)d_in[7];
    const float* gr_Wl  = (const float*)d_in[8];
    const float* gr_Wr  = (const float*)d_in[9];
    const float* gr_att = (const float*)d_in[10];
    const float* gr_b   = (const float*)d_in[11];
    const float* cl_Wf  = (const float*)d_in[12];
    const float* cl_bf  = (const float*)d_in[13];
    const float* cl_Ws  = (const float*)d_in[14];
    const float* cl_bs  = (const float*)d_in[15];
    const float* cr_Wf  = (const float*)d_in[16];
    const float* cr_bf  = (const float*)d_in[17];
    const float* cr_Ws  = (const float*)d_in[18];
    const float* cr_bs  = (const float*)d_in[19];
    const float* node_W = (const float*)d_in[20];
    const float* node_b = (const float*)d_in[21];
    const float* W1     = (const float*)d_in[22];
    const float* b1     = (const float*)d_in[23];
    const float* W2     = (const float*)d_in[24];
    const float* b2     = (const float*)d_in[25];

    float *XM, *XO, *NM, *NO, *XL, *XR, *Fd, *Fs, *Sd, *Ss;
    cudaGetSymbolAddress((void**)&XM, g_XM);
    cudaGetSymbolAddress((void**)&XO, g_XO);
    cudaGetSymbolAddress((void**)&NM, g_NM);
    cudaGetSymbolAddress((void**)&NO, g_NO);
    cudaGetSymbolAddress((void**)&XL, g_XL);
    cudaGetSymbolAddress((void**)&XR, g_XR);
    cudaGetSymbolAddress((void**)&Fd, g_Fd);
    cudaGetSymbolAddress((void**)&Fs, g_Fs);
    cudaGetSymbolAddress((void**)&Sd, g_Sd);
    cudaGetSymbolAddress((void**)&Ss, g_Ss);

    const int maxSmem = 4 * 128 * (Hd + 8) * 2;   // K=128 case: 139264 B
    cudaFuncSetAttribute(gemm_bf16s_kernel,
                         cudaFuncAttributeMaxDynamicSharedMemorySize, maxSmem);

    const int MT = NNODE / 128;   // 160 M-tiles

    auto gemm = [&](const float* A, const float* W, const float* bias, float* C,
                    int K, int Ntot) {
        dim3 grid(MT, Ntot / 128);
        const int smem = 4 * 128 * (K + 8) * 2;
        gemm_bf16s_kernel<<<grid, 256, smem>>>(A, W, bias, C, K, Ntot);
    };

    // encoder
    gemm(x_my,  W_enc, b_enc, XM, CDm, Hd);
    gemm(x_opp, W_enc, b_enc, XO, CDm, Hd);

    for (int l = 0; l < 2; l++) {
        const float* Wl_b = gb_Wl + l*Hd*512;
        const float* Wr_b = gb_Wr + l*Hd*512;
        const float* Wl_r = gr_Wl + l*Hd*512;
        const float* Wr_r = gr_Wr + l*Hd*512;
        const float* att_b = gb_att + l*4*Hd;
        const float* att_r = gr_att + l*4*Hd;
        const float* bb = gb_b + l*Hd;
        const float* br = gr_b + l*Hd;
        const float* clWf = cl_Wf + l*2*Hd*Hd;  const float* clWs = cl_Ws + l*2*Hd*Hd;
        const float* crWf = cr_Wf + l*2*Hd*Hd;  const float* crWs = cr_Ws + l*2*Hd*Hd;
        const float* clbf = cl_bf + l*Hd;  const float* clbs = cl_bs + l*Hd;
        const float* crbf = cr_bf + l*Hd;  const float* crbs = cr_bs + l*Hd;
        const float* nW = node_W + l*Hd*Hd;
        const float* nb = node_b + l*Hd;

        // ---- new_xo = gat_beats(xm -> xo) + cg_loses(xm -> xo) ----
        gemm(XM, Wl_b, nullptr, XL, Hd, 512);
        gemm(XO, Wr_b, nullptr, XR, Hd, 512);
        gat_edge_kernel<<<NG, 256>>>(XL, XR, att_b, bb, NO, 0);

        gemm(XO, clWf,          clbf,    Fd, Hd, Hd);   // dst half (+bias)
        gemm(XM, clWf + Hd*Hd,  nullptr, Fs, Hd, Hd);   // src half
        gemm(XO, clWs,          clbs,    Sd, Hd, Hd);
        gemm(XM, clWs + Hd*Hd,  nullptr, Ss, Hd, Hd);
        cg_edge_kernel<<<NG, 256>>>(Fd, Fs, Sd, Ss, XO, NO, 1);

        // ---- new_xm = cg_rev(xo -> xm) + gat_rev(xo -> xm) ----
        gemm(XM, crWf,          crbf,    Fd, Hd, Hd);
        gemm(XO, crWf + Hd*Hd,  nullptr, Fs, Hd, Hd);
        gemm(XM, crWs,          crbs,    Sd, Hd, Hd);
        gemm(XO, crWs + Hd*Hd,  nullptr, Ss, Hd, Hd);
        cg_edge_kernel<<<NG, 256>>>(Fd, Fs, Sd, Ss, XM, NM, 0);

        gemm(XO, Wl_r, nullptr, XL, Hd, 512);
        gemm(XM, Wr_r, nullptr, XR, Hd, 512);
        gat_edge_kernel<<<NG, 256>>>(XL, XR, att_r, br, NM, 1);

        // ---- node linear ----
        gemm(NM, nW, nb, XM, Hd, Hd);
        gemm(NO, nW, nb, XO, Hd, Hd);
    }

    head_kernel<<<NG, 128>>>(XM, XO, W1, b1, W2, b2, (float*)d_out);
}

// round 11
// speedup vs baseline: 1.3691x; 1.3691x over previous
#include <cuda_runtime.h>
#include <cuda_bf16.h>
#include <cstdint>

typedef unsigned long long u64;

// ============================================================================
// Round 11 (= round 9/10 resubmit after consecutive infra failures):
// HMMA split-bf16 multi-kernel, GEMM v2.
//  - merged 3-term k-loop (fragments loaded once per k-step)
//  - 512 threads / block (16 warps, 4x4), warp tile 32x32
//  - dual-weight support fuses CGConv f/s GEMMs (N=256 launches)
// ============================================================================

namespace {
constexpr int NNODE = 20480;   // 2048 graphs * 10 nodes
constexpr int NG    = 2048;
constexpr int Hd    = 128;
constexpr int CDm   = 32;
}

// -------- global scratch --------
__device__ float g_XM[NNODE*Hd];
__device__ float g_XO[NNODE*Hd];
__device__ float g_NM[NNODE*Hd];
__device__ float g_NO[NNODE*Hd];
__device__ float g_XL[NNODE*512];
__device__ float g_XR[NNODE*512];
__device__ float g_FDSD[NNODE*256];   // cols 0-127: f(dst)+bias, 128-255: s(dst)+bias
__device__ float g_FSSS[NNODE*256];   // cols 0-127: f(src),      128-255: s(src)

__device__ __forceinline__ void mma16816(float* d, const uint32_t* a,
                                         uint32_t b0, uint32_t b1) {
    asm volatile(
        "mma.sync.aligned.m16n8k16.row.col.f32.bf16.bf16.f32 "
        "{%0,%1,%2,%3}, {%4,%5,%6,%7}, {%8,%9}, {%0,%1,%2,%3};"
        : "+f"(d[0]), "+f"(d[1]), "+f"(d[2]), "+f"(d[3])
        : "r"(a[0]), "r"(a[1]), "r"(a[2]), "r"(a[3]), "r"(b0), "r"(b1));
}

// ============================================================================
// GEMM v2: C[m0:m0+128, n0:n0+128] = A[:,K] @ W[K,*] (+bias), split-bf16 3-term.
// If Wb != null: dual mode — column-block 0 uses Wa/biasa, block 1 uses Wb/biasb,
// each weight is [K,128]; C has Ntot columns.
// ============================================================================
extern "C" __global__ void __launch_bounds__(512, 1)
gemm_v2_kernel(const float* __restrict__ A,
               const float* __restrict__ Wa, const float* __restrict__ Wb,
               const float* __restrict__ biasa, const float* __restrict__ biasb,
               float* __restrict__ C, int K, int Ntot)
{
    extern __shared__ __align__(16) char smem_raw[];
    __nv_bfloat16* s = (__nv_bfloat16*)smem_raw;
    const int KP = K + 8;
    __nv_bfloat16* Ah = s;
    __nv_bfloat16* Al = s + 128*KP;
    __nv_bfloat16* Bh = s + 2*128*KP;
    __nv_bfloat16* Bl = s + 3*128*KP;

    const int t  = threadIdx.x;
    const int m0 = blockIdx.x * 128;
    const int n0 = blockIdx.y * 128;

    const float* Wp;  const float* bp;  int wstride, wcol0;
    if (Wb != nullptr) {
        Wp = blockIdx.y ? Wb : Wa;
        bp = blockIdx.y ? biasb : biasa;
        wstride = 128; wcol0 = 0;
    } else {
        Wp = Wa; bp = biasa; wstride = Ntot; wcol0 = n0;
    }

    // ---- stage A tile [128, K] ----
    for (int idx = t; idx < 128*K; idx += 512) {
        const int r = idx / K, k = idx - r*K;
        const float a = A[(size_t)(m0 + r)*K + k];
        const __nv_bfloat16 hi = __float2bfloat16(a);
        const __nv_bfloat16 lo = __float2bfloat16(a - __bfloat162float(hi));
        Ah[r*KP + k] = hi;
        Al[r*KP + k] = lo;
    }
    // ---- stage B transposed: Bs[n][k] = W[k][col0+n] ----
    for (int idx = t; idx < 128*K; idx += 512) {
        const int k = idx >> 7, n = idx & 127;
        const float w = Wp[(size_t)k*wstride + wcol0 + n];
        const __nv_bfloat16 hi = __float2bfloat16(w);
        const __nv_bfloat16 lo = __float2bfloat16(w - __bfloat162float(hi));
        Bh[n*KP + k] = hi;
        Bl[n*KP + k] = lo;
    }
    __syncthreads();

    const int wid = t >> 5, lane = t & 31;
    const int wm = wid & 3, wn = wid >> 2;     // 4 (M) x 4 (N) warps
    const int gID = lane >> 2, tig = lane & 3;

    float acc[2][4][4];
#pragma unroll
    for (int mt = 0; mt < 2; mt++)
#pragma unroll
        for (int nt = 0; nt < 4; nt++)
#pragma unroll
            for (int q = 0; q < 4; q++) acc[mt][nt][q] = 0.f;

#pragma unroll 1
    for (int k0 = 0; k0 < K; k0 += 16) {
        uint32_t ah[2][4], al[2][4], bh[4][2], bl[4][2];
#pragma unroll
        for (int mt = 0; mt < 2; mt++) {
            const int row = wm*32 + mt*16 + gID;
            const int off = row*KP + k0 + 2*tig;
            ah[mt][0] = *(const uint32_t*)(Ah + off);
            ah[mt][1] = *(const uint32_t*)(Ah + off + 8*KP);
            ah[mt][2] = *(const uint32_t*)(Ah + off + 8);
            ah[mt][3] = *(const uint32_t*)(Ah + off + 8*KP + 8);
            al[mt][0] = *(const uint32_t*)(Al + off);
            al[mt][1] = *(const uint32_t*)(Al + off + 8*KP);
            al[mt][2] = *(const uint32_t*)(Al + off + 8);
            al[mt][3] = *(const uint32_t*)(Al + off + 8*KP + 8);
        }
#pragma unroll
        for (int nt = 0; nt < 4; nt++) {
            const int col = wn*32 + nt*8 + gID;
            const int off = col*KP + k0 + 2*tig;
            bh[nt][0] = *(const uint32_t*)(Bh + off);
            bh[nt][1] = *(const uint32_t*)(Bh + off + 8);
            bl[nt][0] = *(const uint32_t*)(Bl + off);
            bl[nt][1] = *(const uint32_t*)(Bl + off + 8);
        }
#pragma unroll
        for (int mt = 0; mt < 2; mt++)
#pragma unroll
            for (int nt = 0; nt < 4; nt++) {
                mma16816(acc[mt][nt], ah[mt], bh[nt][0], bh[nt][1]);
                mma16816(acc[mt][nt], ah[mt], bl[nt][0], bl[nt][1]);
                mma16816(acc[mt][nt], al[mt], bh[nt][0], bh[nt][1]);
            }
    }

    // ---- epilogue ----
#pragma unroll
    for (int mt = 0; mt < 2; mt++) {
        const int row = m0 + wm*32 + mt*16 + gID;
#pragma unroll
        for (int nt = 0; nt < 4; nt++) {
            const int col = n0 + wn*32 + nt*8 + 2*tig;
            float2 v0 = make_float2(acc[mt][nt][0], acc[mt][nt][1]);
            float2 v1 = make_float2(acc[mt][nt][2], acc[mt][nt][3]);
            if (bp) {
                const float2 bb = *(const float2*)&bp[(col - n0) + (Wb ? 0 : n0)];
                v0.x += bb.x; v0.y += bb.y;
                v1.x += bb.x; v1.y += bb.y;
            }
            *(float2*)&C[(size_t)row*Ntot + col]       = v0;
            *(float2*)&C[(size_t)(row + 8)*Ntot + col] = v1;
        }
    }
}

// ============================================================================
// GATv2 edge kernel (validated round 8): logits, softmax, aggregate, +bias.
// ============================================================================
extern "C" __global__ void __launch_bounds__(256)
gat_edge_kernel(const float* __restrict__ XL, const float* __restrict__ XR,
                const float* __restrict__ att, const float* __restrict__ bias,
                float* __restrict__ OUT, int accum)
{
    __shared__ float sXL[10*512], sXR[10*512], sLog[40*16], sAtt[512];
    const int g = blockIdx.x, t = threadIdx.x;
    const int wid = t >> 5, lane = t & 31;
    const size_t base = (size_t)g * 5120;

    for (int idx = t; idx < 5120; idx += 256) {
        sXL[idx] = XL[base + idx];
        sXR[idx] = XR[base + idx];
    }
    for (int idx = t; idx < 512; idx += 256) sAtt[idx] = att[idx];
    __syncthreads();

#pragma unroll 1
    for (int pp = 0; pp < 5; pp++) {
        const int p = wid + pp * 8;          // 0..39 = h*10+j
        const int h = p / 10, j = p % 10;
        const float4 xr = *(const float4*)&sXR[j*512 + h*128 + lane*4];
        const float4 at = *(const float4*)&sAtt[h*128 + lane*4];
#pragma unroll
        for (int i = 0; i < 10; i++) {
            const float4 xl = *(const float4*)&sXL[i*512 + h*128 + lane*4];
            float e, s;
            e = xl.x + xr.x; s = at.x * fmaf(e, 0.6f, 0.4f*fabsf(e));
            e = xl.y + xr.y; s = fmaf(at.y, fmaf(e, 0.6f, 0.4f*fabsf(e)), s);
            e = xl.z + xr.z; s = fmaf(at.z, fmaf(e, 0.6f, 0.4f*fabsf(e)), s);
            e = xl.w + xr.w; s = fmaf(at.w, fmaf(e, 0.6f, 0.4f*fabsf(e)), s);
#pragma unroll
            for (int o = 16; o > 0; o >>= 1) s += __shfl_xor_sync(0xffffffffu, s, o);
            if (lane == 0) sLog[p*16 + i] = s;
        }
    }
    __syncthreads();

    if (t < 40) {
        float* lg = sLog + t*16;
        float m = lg[0];
#pragma unroll
        for (int i = 1; i < 10; i++) m = fmaxf(m, lg[i]);
        float a[10]; float sum = 0.f;
#pragma unroll
        for (int i = 0; i < 10; i++) { a[i] = __expf(lg[i] - m); sum += a[i]; }
        const float inv = __fdividef(1.f, sum);
#pragma unroll
        for (int i = 0; i < 10; i++) lg[i] = a[i] * inv;
    }
    __syncthreads();

    {
        const int c = t & 127, rh = t >> 7;
        float accj[5] = {0.f, 0.f, 0.f, 0.f, 0.f};
#pragma unroll
        for (int h = 0; h < 4; h++) {
            float xlh[10];
#pragma unroll
            for (int i = 0; i < 10; i++) xlh[i] = sXL[i*512 + h*128 + c];
#pragma unroll
            for (int jj = 0; jj < 5; jj++) {
                const float* al = sLog + (h*10 + rh*5 + jj)*16;
                float v = accj[jj];
#pragma unroll
                for (int i = 0; i < 10; i++) v = fmaf(al[i], xlh[i], v);
                accj[jj] = v;
            }
        }
        const float bv = bias[c];
#pragma unroll
        for (int jj = 0; jj < 5; jj++) {
            const int j = rh*5 + jj;
            const size_t idx = (size_t)(g*10 + j)*128 + c;
            const float v = accj[jj]*0.25f + bv;
            OUT[idx] = accum ? (OUT[idx] + v) : v;
        }
    }
}

// ============================================================================
// CGConv edge kernel, fused-buffer version.
// FDSD[n,0:128]=Fd(+bias), FDSD[n,128:256]=Sd(+bias); FSSS likewise for src.
// ============================================================================
extern "C" __global__ void __launch_bounds__(256)
cg_edge_kernel(const float* __restrict__ FDSD, const float* __restrict__ FSSS,
               const float* __restrict__ Xd, float* __restrict__ OUT, int accum)
{
    __shared__ float sFd[1280], sFs[1280], sSd[1280], sSs[1280], sXd[1280];
    const int g = blockIdx.x, t = threadIdx.x;
    for (int idx = t; idx < 1280; idx += 256) {
        const int i = idx >> 7, c = idx & 127;
        const size_t b2 = (size_t)(g*10 + i)*256 + c;
        sFd[idx] = FDSD[b2];       sSd[idx] = FDSD[b2 + 128];
        sFs[idx] = FSSS[b2];       sSs[idx] = FSSS[b2 + 128];
        sXd[idx] = Xd[(size_t)(g*10 + i)*128 + c];
    }
    __syncthreads();
    const int c = t & 127, rh = t >> 7;
#pragma unroll
    for (int jj = 0; jj < 5; jj++) {
        const int i = rh*5 + jj;
        const float fd = sFd[i*128 + c];
        const float sd = sSd[i*128 + c];
        float acc = sXd[i*128 + c];
#pragma unroll
        for (int j = 0; j < 10; j++) {
            const float f = fd + sFs[j*128 + c];
            const float s = sd + sSs[j*128 + c];
            const float sig = __fdividef(1.f, 1.f + __expf(-f));
            const float sp  = fmaxf(s, 0.f) + __logf(1.f + __expf(-fabsf(s)));
            acc = fmaf(sig, sp, acc);
        }
        const size_t idx = (size_t)(g*10 + i)*128 + c;
        OUT[idx] = accum ? (OUT[idx] + acc) : acc;
    }
}

// ============================================================================
// Head: per graph — mean pool both types, MLP, write scalar
// ============================================================================
extern "C" __global__ void __launch_bounds__(128)
head_kernel(const float* __restrict__ XM, const float* __restrict__ XO,
            const float* __restrict__ W1, const float* __restrict__ b1,
            const float* __restrict__ W2, const float* __restrict__ b2,
            float* __restrict__ out)
{
    __shared__ float pool[256], red[128];
    const int g = blockIdx.x, t = threadIdx.x;
    {
        float pm = 0.f, po = 0.f;
#pragma unroll
        for (int r = 0; r < 10; r++) {
            pm += XM[(size_t)(g*10 + r)*128 + t];
            po += XO[(size_t)(g*10 + r)*128 + t];
        }
        pool[t] = pm * 0.1f;
        pool[128 + t] = po * 0.1f;
    }
    __syncthreads();
    {
        float a = 0.f;
#pragma unroll 4
        for (int k = 0; k < 256; k++) a = fmaf(pool[k], W1[k*128 + t], a);
        a += b1[t];
        a = (a >= 0.f) ? a : 128.f * a;     // LeakyReLU slope = final_dim
        red[t] = a * W2[t];
    }
    __syncthreads();
    if (t < 32) {
        float v = red[t] + red[t+32] + red[t+64] + red[t+96];
#pragma unroll
        for (int o = 16; o > 0; o >>= 1) v += __shfl_xor_sync(0xffffffffu, v, o);
        if (t == 0) out[g] = v + b2[0];
    }
}

// ============================================================================
// Host launcher
// ============================================================================
extern "C" void kernel_launch(void* const* d_in, const int* in_sizes, int n_in,
                              void* d_out, int out_size)
{
    const float* x_my   = (const float*)d_in[0];
    const float* x_opp  = (const float*)d_in[1];
    const float* W_enc  = (const float*)d_in[2];
    const float* b_enc  = (const float*)d_in[3];
    const float* gb_Wl  = (const float*)d_in[4];
    const float* gb_Wr  = (const float*)d_in[5];
    const float* gb_att = (const float*)d_in[6];
    const float* gb_b   = (const float*)d_in[7];
    const float* gr_Wl  = (const float*)d_in[8];
    const float* gr_Wr  = (const float*)d_in[9];
    const float* gr_att = (const float*)d_in[10];
    const float* gr_b   = (const float*)d_in[11];
    const float* cl_Wf  = (const float*)d_in[12];
    const float* cl_bf  = (const float*)d_in[13];
    const float* cl_Ws  = (const float*)d_in[14];
    const float* cl_bs  = (const float*)d_in[15];
    const float* cr_Wf  = (const float*)d_in[16];
    const float* cr_bf  = (const float*)d_in[17];
    const float* cr_Ws  = (const float*)d_in[18];
    const float* cr_bs  = (const float*)d_in[19];
    const float* node_W = (const float*)d_in[20];
    const float* node_b = (const float*)d_in[21];
    const float* W1     = (const float*)d_in[22];
    const float* b1     = (const float*)d_in[23];
    const float* W2     = (const float*)d_in[24];
    const float* b2     = (const float*)d_in[25];

    float *XM, *XO, *NM, *NO, *XL, *XR, *FDSD, *FSSS;
    cudaGetSymbolAddress((void**)&XM, g_XM);
    cudaGetSymbolAddress((void**)&XO, g_XO);
    cudaGetSymbolAddress((void**)&NM, g_NM);
    cudaGetSymbolAddress((void**)&NO, g_NO);
    cudaGetSymbolAddress((void**)&XL, g_XL);
    cudaGetSymbolAddress((void**)&XR, g_XR);
    cudaGetSymbolAddress((void**)&FDSD, g_FDSD);
    cudaGetSymbolAddress((void**)&FSSS, g_FSSS);

    const int maxSmem = 4 * 128 * (Hd + 8) * 2;   // 139264 B
    cudaFuncSetAttribute(gemm_v2_kernel,
                         cudaFuncAttributeMaxDynamicSharedMemorySize, maxSmem);

    const int MT = NNODE / 128;   // 160 M-tiles

    auto gemm = [&](const float* A, const float* Wa, const float* Wb,
                    const float* ba, const float* bb, float* C,
                    int K, int Ntot) {
        dim3 grid(MT, Ntot / 128);
        const int smem = 4 * 128 * (K + 8) * 2;
        gemm_v2_kernel<<<grid, 512, smem>>>(A, Wa, Wb, ba, bb, C, K, Ntot);
    };

    // encoder
    gemm(x_my,  W_enc, nullptr, b_enc, nullptr, XM, CDm, Hd);
    gemm(x_opp, W_enc, nullptr, b_enc, nullptr, XO, CDm, Hd);

    for (int l = 0; l < 2; l++) {
        const float* Wl_b = gb_Wl + l*Hd*512;
        const float* Wr_b = gb_Wr + l*Hd*512;
        const float* Wl_r = gr_Wl + l*Hd*512;
        const float* Wr_r = gr_Wr + l*Hd*512;
        const float* att_b = gb_att + l*4*Hd;
        const float* att_r = gr_att + l*4*Hd;
        const float* bb = gb_b + l*Hd;
        const float* br = gr_b + l*Hd;
        const float* clWf = cl_Wf + l*2*Hd*Hd;  const float* clWs = cl_Ws + l*2*Hd*Hd;
        const float* crWf = cr_Wf + l*2*Hd*Hd;  const float* crWs = cr_Ws + l*2*Hd*Hd;
        const float* clbf = cl_bf + l*Hd;  const float* clbs = cl_bs + l*Hd;
        const float* crbf = cr_bf + l*Hd;  const float* crbs = cr_bs + l*Hd;
        const float* nW = node_W + l*Hd*Hd;
        const float* nb = node_b + l*Hd;

        // ---- new_xo = gat_beats(xm -> xo) + cg_loses(xm -> xo) ----
        gemm(XM, Wl_b, nullptr, nullptr, nullptr, XL, Hd, 512);
        gemm(XO, Wr_b, nullptr, nullptr, nullptr, XR, Hd, 512);
        gat_edge_kernel<<<NG, 256>>>(XL, XR, att_b, bb, NO, 0);

        gemm(XO, clWf,         clWs,         clbf,    clbs,    FDSD, Hd, 256);
        gemm(XM, clWf + Hd*Hd, clWs + Hd*Hd, nullptr, nullptr, FSSS, Hd, 256);
        cg_edge_kernel<<<NG, 256>>>(FDSD, FSSS, XO, NO, 1);

        // ---- new_xm = cg_rev(xo -> xm) + gat_rev(xo -> xm) ----
        gemm(XM, crWf,         crWs,         crbf,    crbs,    FDSD, Hd, 256);
        gemm(XO, crWf + Hd*Hd, crWs + Hd*Hd, nullptr, nullptr, FSSS, Hd, 256);
        cg_edge_kernel<<<NG, 256>>>(FDSD, FSSS, XM, NM, 0);

        gemm(XO, Wl_r, nullptr, nullptr, nullptr, XL, Hd, 512);
        gemm(XM, Wr_r, nullptr, nullptr, nullptr, XR, Hd, 512);
        gat_edge_kernel<<<NG, 256>>>(XL, XR, att_r, br, NM, 1);

        // ---- node linear ----
        gemm(NM, nW, nullptr, nb, nullptr, XM, Hd, Hd);
        gemm(NO, nW, nullptr, nb, nullptr, XO, Hd, Hd);
    }

    head_kernel<<<NG, 128>>>(XM, XO, W1, b1, W2, b2, (float*)d_out);
}

// round 12
// speedup vs baseline: 1.3870x; 1.0131x over previous
#include <cuda_runtime.h>
#include <cuda_bf16.h>
#include <cstdint>

typedef unsigned long long u64;
typedef __nv_bfloat16 bf16;

// ============================================================================
// Round 12: HMMA split-bf16 multi-kernel, GEMM v3.
//  - ldmatrix.m8n8.x4 fragment loads (8 LDSM vs 48 LDS.32 per k-step)
//  - weights pre-converted once per call to tile-major bf16 hi/lo
//  - fused GAT+CGConv edge kernel (both relations sum into same dst)
// ============================================================================

namespace {
constexpr int NNODE = 20480;   // 2048 graphs * 10 nodes
constexpr int NG    = 2048;
constexpr int Hd    = 128;
constexpr int CDm   = 32;
constexpr size_t TSZ = 16384;         // bf16 elems per 128x128 tile
constexpr size_t ENC_SZ = 4096;       // 128x32 enc tile
constexpr size_t LAYER_TILES = 25;
constexpr size_t WBUF_SZ = ENC_SZ + 2*LAYER_TILES*TSZ;  // 823296
}

__host__ __device__ inline size_t LOFF(int l) { return ENC_SZ + (size_t)l*LAYER_TILES*TSZ; }

// -------- global scratch --------
__device__ float g_XM[NNODE*Hd];
__device__ float g_XO[NNODE*Hd];
__device__ float g_NM[NNODE*Hd];
__device__ float g_NO[NNODE*Hd];
__device__ float g_XL[NNODE*512];
__device__ float g_XR[NNODE*512];
__device__ float g_FDSD[NNODE*256];
__device__ float g_FSSS[NNODE*256];
__device__ bf16  g_Whi[WBUF_SZ];
__device__ bf16  g_Wlo[WBUF_SZ];

__device__ __forceinline__ void mma16816(float* d, const uint32_t* a,
                                         uint32_t b0, uint32_t b1) {
    asm volatile(
        "mma.sync.aligned.m16n8k16.row.col.f32.bf16.bf16.f32 "
        "{%0,%1,%2,%3}, {%4,%5,%6,%7}, {%8,%9}, {%0,%1,%2,%3};"
        : "+f"(d[0]), "+f"(d[1]), "+f"(d[2]), "+f"(d[3])
        : "r"(a[0]), "r"(a[1]), "r"(a[2]), "r"(a[3]), "r"(b0), "r"(b1));
}

#define LDSM4(r, addr) \
    asm volatile("ldmatrix.sync.aligned.m8n8.x4.shared.b16 {%0,%1,%2,%3}, [%4];" \
                 : "=r"((r)[0]), "=r"((r)[1]), "=r"((r)[2]), "=r"((r)[3]) \
                 : "r"(addr))

// ============================================================================
// Weight prep kernels: transpose+split fp32 W[K,N] -> tile-major bf16 [n][K]
// ============================================================================
extern "C" __global__ void __launch_bounds__(256)
prep_gat(const float* __restrict__ gbWl, const float* __restrict__ gbWr,
         const float* __restrict__ grWl, const float* __restrict__ grWr,
         bf16* __restrict__ hi, bf16* __restrict__ lo)
{
    const int b = blockIdx.x;                 // 32 blocks
    const int l = b >> 4, tq = (b >> 2) & 3, tile = b & 3;
    const float* src;
    if      (tq == 0) src = gbWl;
    else if (tq == 1) src = gbWr;
    else if (tq == 2) src = grWl;
    else              src = grWr;
    src += (size_t)l * 128 * 512;
    const size_t dst = LOFF(l) + (size_t)tq*4*TSZ + (size_t)tile*TSZ;
    for (int idx = threadIdx.x; idx < 16384; idx += 256) {
        const int nl = idx >> 7, k = idx & 127;
        const float w = src[k*512 + tile*128 + nl];
        const bf16 h = __float2bfloat16(w);
        hi[dst + nl*128 + k] = h;
        lo[dst + nl*128 + k] = __float2bfloat16(w - __bfloat162float(h));
    }
}

extern "C" __global__ void __launch_bounds__(256)
prep_cg(const float* __restrict__ clWf, const float* __restrict__ clWs,
        const float* __restrict__ crWf, const float* __restrict__ crWs,
        bf16* __restrict__ hi, bf16* __restrict__ lo)
{
    const int b = blockIdx.x;                 // 16 blocks
    const int l = b >> 3, q = b & 7;
    const int buf = q >> 1, tile = q & 1;     // buf: 0 CLD,1 CLS,2 CRD,3 CRS
    const float* fw = (buf < 2) ? clWf : crWf;
    const float* sw = (buf < 2) ? clWs : crWs;
    const float* src = (tile ? sw : fw) + (size_t)l*256*128 + ((buf & 1) ? 128*128 : 0);
    const size_t dst = LOFF(l) + (size_t)(16 + buf*2 + tile)*TSZ;
    for (int idx = threadIdx.x; idx < 16384; idx += 256) {
        const int nl = idx >> 7, k = idx & 127;
        const float w = src[k*128 + nl];
        const bf16 h = __float2bfloat16(w);
        hi[dst + nl*128 + k] = h;
        lo[dst + nl*128 + k] = __float2bfloat16(w - __bfloat162float(h));
    }
}

extern "C" __global__ void __launch_bounds__(256)
prep_misc(const float* __restrict__ Wenc, const float* __restrict__ nodeW,
          bf16* __restrict__ hi, bf16* __restrict__ lo)
{
    const int b = blockIdx.x;                 // 3 blocks
    if (b == 0) {
        for (int idx = threadIdx.x; idx < 4096; idx += 256) {
            const int nl = idx >> 5, k = idx & 31;
            const float w = Wenc[k*128 + nl];
            const bf16 h = __float2bfloat16(w);
            hi[nl*32 + k] = h;
            lo[nl*32 + k] = __float2bfloat16(w - __bfloat162float(h));
        }
    } else {
        const int l = b - 1;
        const float* src = nodeW + (size_t)l*128*128;
        const size_t dst = LOFF(l) + 24*TSZ;
        for (int idx = threadIdx.x; idx < 16384; idx += 256) {
            const int nl = idx >> 7, k = idx & 127;
            const float w = src[k*128 + nl];
            const bf16 h = __float2bfloat16(w);
            hi[dst + nl*128 + k] = h;
            lo[dst + nl*128 + k] = __float2bfloat16(w - __bfloat162float(h));
        }
    }
}

// ============================================================================
// GEMM v3: C[m0+128, ty*128..+128] = A[:,K] @ Wtile (+bias), split-bf16 3-term.
// W: tile-major bf16 hi/lo, tile = blockIdx.y. ldmatrix fragment loads.
// Dual-bias: if biasb, tile 1 uses biasb with local col index.
// ============================================================================
extern "C" __global__ void __launch_bounds__(512, 1)
gemm_v3_kernel(const float* __restrict__ A,
               const bf16* __restrict__ Whi, const bf16* __restrict__ Wlo,
               const float* __restrict__ biasa, const float* __restrict__ biasb,
               float* __restrict__ C, int K, int Ntot)
{
    extern __shared__ __align__(16) char smem_raw[];
    bf16* s = (bf16*)smem_raw;
    const int KP = K + 8;
    bf16* Ah = s;
    bf16* Al = s +   128*KP;
    bf16* Bh = s + 2*128*KP;
    bf16* Bl = s + 3*128*KP;

    const int t  = threadIdx.x;
    const int m0 = blockIdx.x * 128;
    const int ty = blockIdx.y;
    const int n0 = ty * 128;

    // ---- stage A tile [128, K] fp32 -> hi/lo ----
    for (int idx = t; idx < 128*K; idx += 512) {
        const int r = idx / K, k = idx - r*K;
        const float a = A[(size_t)(m0 + r)*K + k];
        const bf16 hv = __float2bfloat16(a);
        Ah[r*KP + k] = hv;
        Al[r*KP + k] = __float2bfloat16(a - __bfloat162float(hv));
    }
    // ---- stage B tile: straight uint4 copy from prepped bf16 ----
    {
        const bf16* wh = Whi + (size_t)ty*128*K;
        const bf16* wl = Wlo + (size_t)ty*128*K;
        const int c8n = K >> 3;
        for (int idx = t; idx < 128*c8n; idx += 512) {
            const int row = idx / c8n, c8 = idx - row*c8n;
            *(uint4*)&Bh[row*KP + c8*8] = ((const uint4*)(wh + row*K))[c8];
            *(uint4*)&Bl[row*KP + c8*8] = ((const uint4*)(wl + row*K))[c8];
        }
    }
    __syncthreads();

    const int wid = t >> 5, lane = t & 31;
    const int wm = wid & 3, wn = wid >> 2;     // 4 (M) x 4 (N) warps
    const int gID = lane >> 2, tig = lane & 3;

    // ldmatrix per-lane base addresses (bytes, shared space)
    const uint32_t laneOff = (uint32_t)(((lane & 15)*KP + (lane >> 4)*8) * 2);
    const uint32_t aHiB = (uint32_t)__cvta_generic_to_shared(Ah) + (uint32_t)(wm*32*KP*2) + laneOff;
    const uint32_t aLoB = (uint32_t)__cvta_generic_to_shared(Al) + (uint32_t)(wm*32*KP*2) + laneOff;
    const uint32_t bHiB = (uint32_t)__cvta_generic_to_shared(Bh) + (uint32_t)(wn*32*KP*2) + laneOff;
    const uint32_t bLoB = (uint32_t)__cvta_generic_to_shared(Bl) + (uint32_t)(wn*32*KP*2) + laneOff;
    const uint32_t mtOff = (uint32_t)(16*KP*2);

    float acc[2][4][4];
#pragma unroll
    for (int mt = 0; mt < 2; mt++)
#pragma unroll
        for (int nt = 0; nt < 4; nt++)
#pragma unroll
            for (int q = 0; q < 4; q++) acc[mt][nt][q] = 0.f;

    const int KS = K >> 4;
#pragma unroll 1
    for (int ks = 0; ks < KS; ks++) {
        const uint32_t ko = (uint32_t)(ks * 32);
        uint32_t ah[2][4], al[2][4], b0h[4], b1h[4], b0l[4], b1l[4];
        LDSM4(ah[0], aHiB + ko);
        LDSM4(ah[1], aHiB + mtOff + ko);
        LDSM4(al[0], aLoB + ko);
        LDSM4(al[1], aLoB + mtOff + ko);
        LDSM4(b0h, bHiB + ko);            // nt0(r0,r2), nt1(r1,r3)
        LDSM4(b1h, bHiB + mtOff + ko);    // nt2, nt3
        LDSM4(b0l, bLoB + ko);
        LDSM4(b1l, bLoB + mtOff + ko);
#pragma unroll
        for (int mt = 0; mt < 2; mt++) {
            // nt0
            mma16816(acc[mt][0], ah[mt], b0h[0], b0h[2]);
            mma16816(acc[mt][0], ah[mt], b0l[0], b0l[2]);
            mma16816(acc[mt][0], al[mt], b0h[0], b0h[2]);
            // nt1
            mma16816(acc[mt][1], ah[mt], b0h[1], b0h[3]);
            mma16816(acc[mt][1], ah[mt], b0l[1], b0l[3]);
            mma16816(acc[mt][1], al[mt], b0h[1], b0h[3]);
            // nt2
            mma16816(acc[mt][2], ah[mt], b1h[0], b1h[2]);
            mma16816(acc[mt][2], ah[mt], b1l[0], b1l[2]);
            mma16816(acc[mt][2], al[mt], b1h[0], b1h[2]);
            // nt3
            mma16816(acc[mt][3], ah[mt], b1h[1], b1h[3]);
            mma16816(acc[mt][3], ah[mt], b1l[1], b1l[3]);
            mma16816(acc[mt][3], al[mt], b1h[1], b1h[3]);
        }
    }

    // ---- epilogue ----
    const bool dual = (biasb != nullptr);
    const float* bp = (dual && ty) ? biasb : biasa;
#pragma unroll
    for (int mt = 0; mt < 2; mt++) {
        const int row = m0 + wm*32 + mt*16 + gID;
#pragma unroll
        for (int nt = 0; nt < 4; nt++) {
            const int col = n0 + wn*32 + nt*8 + 2*tig;
            float2 v0 = make_float2(acc[mt][nt][0], acc[mt][nt][1]);
            float2 v1 = make_float2(acc[mt][nt][2], acc[mt][nt][3]);
            if (bp) {
                const int bi = dual ? (col - n0) : col;
                const float2 bb = *(const float2*)&bp[bi];
                v0.x += bb.x; v0.y += bb.y;
                v1.x += bb.x; v1.y += bb.y;
            }
            *(float2*)&C[(size_t)row*Ntot + col]       = v0;
            *(float2*)&C[(size_t)(row + 8)*Ntot + col] = v1;
        }
    }
}

// ============================================================================
// Fused edge kernel: OUT = GATv2(XL,XR,att)+gbias + CGConv(FDSD,FSSS)+Xd
// Dynamic smem: 17792 floats.
// ============================================================================
extern "C" __global__ void __launch_bounds__(256)
edge_fused_kernel(const float* __restrict__ XL, const float* __restrict__ XR,
                  const float* __restrict__ att, const float* __restrict__ gbias,
                  const float* __restrict__ FDSD, const float* __restrict__ FSSS,
                  const float* __restrict__ Xd, float* __restrict__ OUT)
{
    extern __shared__ float sm[];
    float* sXL  = sm;            // 5120
    float* sXR  = sm + 5120;     // 5120
    float* sFd  = sm + 10240;    // 1280
    float* sFs  = sm + 11520;
    float* sSd  = sm + 12800;
    float* sSs  = sm + 14080;
    float* sXd  = sm + 15360;    // 1280
    float* sLog = sm + 16640;    // 640
    float* sAtt = sm + 17280;    // 512

    const int g = blockIdx.x, t = threadIdx.x;
    const int wid = t >> 5, lane = t & 31;
    const size_t base = (size_t)g * 5120;

    for (int idx = t; idx < 5120; idx += 256) {
        sXL[idx] = XL[base + idx];
        sXR[idx] = XR[base + idx];
    }
    for (int idx = t; idx < 1280; idx += 256) {
        const int i = idx >> 7, c = idx & 127;
        const size_t b2 = (size_t)(g*10 + i)*256 + c;
        sFd[idx] = FDSD[b2];  sSd[idx] = FDSD[b2 + 128];
        sFs[idx] = FSSS[b2];  sSs[idx] = FSSS[b2 + 128];
        sXd[idx] = Xd[(size_t)(g*10 + i)*128 + c];
    }
    for (int idx = t; idx < 512; idx += 256) sAtt[idx] = att[idx];
    __syncthreads();

    // GAT logits: warp per (h,j); leaky(e) = 0.6e + 0.4|e|
#pragma unroll 1
    for (int pp = 0; pp < 5; pp++) {
        const int p = wid + pp * 8;
        const int h = p / 10, j = p % 10;
        const float4 xr = *(const float4*)&sXR[j*512 + h*128 + lane*4];
        const float4 at = *(const float4*)&sAtt[h*128 + lane*4];
#pragma unroll
        for (int i = 0; i < 10; i++) {
            const float4 xl = *(const float4*)&sXL[i*512 + h*128 + lane*4];
            float e, sv;
            e = xl.x + xr.x; sv = at.x * fmaf(e, 0.6f, 0.4f*fabsf(e));
            e = xl.y + xr.y; sv = fmaf(at.y, fmaf(e, 0.6f, 0.4f*fabsf(e)), sv);
            e = xl.z + xr.z; sv = fmaf(at.z, fmaf(e, 0.6f, 0.4f*fabsf(e)), sv);
            e = xl.w + xr.w; sv = fmaf(at.w, fmaf(e, 0.6f, 0.4f*fabsf(e)), sv);
#pragma unroll
            for (int o = 16; o > 0; o >>= 1) sv += __shfl_xor_sync(0xffffffffu, sv, o);
            if (lane == 0) sLog[p*16 + i] = sv;
        }
    }
    __syncthreads();

    if (t < 40) {
        float* lg = sLog + t*16;
        float m = lg[0];
#pragma unroll
        for (int i = 1; i < 10; i++) m = fmaxf(m, lg[i]);
        float a[10]; float sum = 0.f;
#pragma unroll
        for (int i = 0; i < 10; i++) { a[i] = __expf(lg[i] - m); sum += a[i]; }
        const float inv = __fdividef(1.f, sum);
#pragma unroll
        for (int i = 0; i < 10; i++) lg[i] = a[i] * inv;
    }
    __syncthreads();

    {
        const int c = t & 127, rh = t >> 7;
        // GAT aggregate
        float accj[5] = {0.f, 0.f, 0.f, 0.f, 0.f};
#pragma unroll
        for (int h = 0; h < 4; h++) {
            float xlh[10];
#pragma unroll
            for (int i = 0; i < 10; i++) xlh[i] = sXL[i*512 + h*128 + c];
#pragma unroll
            for (int jj = 0; jj < 5; jj++) {
                const float* al = sLog + (h*10 + rh*5 + jj)*16;
                float v = accj[jj];
#pragma unroll
                for (int i = 0; i < 10; i++) v = fmaf(al[i], xlh[i], v);
                accj[jj] = v;
            }
        }
        const float bv = gbias[c];
#pragma unroll
        for (int jj = 0; jj < 5; jj++) {
            const int i = rh*5 + jj;
            // CGConv sum + residual
            const float fd = sFd[i*128 + c];
            const float sd = sSd[i*128 + c];
            float cg = sXd[i*128 + c];
#pragma unroll
            for (int j = 0; j < 10; j++) {
                const float f = fd + sFs[j*128 + c];
                const float s2 = sd + sSs[j*128 + c];
                const float sig = __fdividef(1.f, 1.f + __expf(-f));
                const float sp  = fmaxf(s2, 0.f) + __logf(1.f + __expf(-fabsf(s2)));
                cg = fmaf(sig, sp, cg);
            }
            OUT[(size_t)(g*10 + i)*128 + c] = accj[jj]*0.25f + bv + cg;
        }
    }
}

// ============================================================================
// Head: per graph — mean pool both types, MLP, write scalar
// ============================================================================
extern "C" __global__ void __launch_bounds__(128)
head_kernel(const float* __restrict__ XM, const float* __restrict__ XO,
            const float* __restrict__ W1, const float* __restrict__ b1,
            const float* __restrict__ W2, const float* __restrict__ b2,
            float* __restrict__ out)
{
    __shared__ float pool[256], red[128];
    const int g = blockIdx.x, t = threadIdx.x;
    {
        float pm = 0.f, po = 0.f;
#pragma unroll
        for (int r = 0; r < 10; r++) {
            pm += XM[(size_t)(g*10 + r)*128 + t];
            po += XO[(size_t)(g*10 + r)*128 + t];
        }
        pool[t] = pm * 0.1f;
        pool[128 + t] = po * 0.1f;
    }
    __syncthreads();
    {
        float a = 0.f;
#pragma unroll 4
        for (int k = 0; k < 256; k++) a = fmaf(pool[k], W1[k*128 + t], a);
        a += b1[t];
        a = (a >= 0.f) ? a : 128.f * a;
        red[t] = a * W2[t];
    }
    __syncthreads();
    if (t < 32) {
        float v = red[t] + red[t+32] + red[t+64] + red[t+96];
#pragma unroll
        for (int o = 16; o > 0; o >>= 1) v += __shfl_xor_sync(0xffffffffu, v, o);
        if (t == 0) out[g] = v + b2[0];
    }
}

// ============================================================================
// Host launcher
// ============================================================================
extern "C" void kernel_launch(void* const* d_in, const int* in_sizes, int n_in,
                              void* d_out, int out_size)
{
    const float* x_my   = (const float*)d_in[0];
    const float* x_opp  = (const float*)d_in[1];
    const float* W_enc  = (const float*)d_in[2];
    const float* b_enc  = (const float*)d_in[3];
    const float* gb_Wl  = (const float*)d_in[4];
    const float* gb_Wr  = (const float*)d_in[5];
    const float* gb_att = (const float*)d_in[6];
    const float* gb_b   = (const float*)d_in[7];
    const float* gr_Wl  = (const float*)d_in[8];
    const float* gr_Wr  = (const float*)d_in[9];
    const float* gr_att = (const float*)d_in[10];
    const float* gr_b   = (const float*)d_in[11];
    const float* cl_Wf  = (const float*)d_in[12];
    const float* cl_bf  = (const float*)d_in[13];
    const float* cl_Ws  = (const float*)d_in[14];
    const float* cl_bs  = (const float*)d_in[15];
    const float* cr_Wf  = (const float*)d_in[16];
    const float* cr_bf  = (const float*)d_in[17];
    const float* cr_Ws  = (const float*)d_in[18];
    const float* cr_bs  = (const float*)d_in[19];
    const float* node_W = (const float*)d_in[20];
    const float* node_b = (const float*)d_in[21];
    const float* W1     = (const float*)d_in[22];
    const float* b1     = (const float*)d_in[23];
    const float* W2     = (const float*)d_in[24];
    const float* b2     = (const float*)d_in[25];

    float *XM, *XO, *NM, *NO, *XL, *XR, *FDSD, *FSSS;
    bf16 *WH, *WL;
    cudaGetSymbolAddress((void**)&XM, g_XM);
    cudaGetSymbolAddress((void**)&XO, g_XO);
    cudaGetSymbolAddress((void**)&NM, g_NM);
    cudaGetSymbolAddress((void**)&NO, g_NO);
    cudaGetSymbolAddress((void**)&XL, g_XL);
    cudaGetSymbolAddress((void**)&XR, g_XR);
    cudaGetSymbolAddress((void**)&FDSD, g_FDSD);
    cudaGetSymbolAddress((void**)&FSSS, g_FSSS);
    cudaGetSymbolAddress((void**)&WH, g_Whi);
    cudaGetSymbolAddress((void**)&WL, g_Wlo);

    const int gemmSmemMax = 4 * 128 * (Hd + 8) * 2;       // 139264
    cudaFuncSetAttribute(gemm_v3_kernel,
                         cudaFuncAttributeMaxDynamicSharedMemorySize, gemmSmemMax);
    const int edgeSmem = 17792 * 4;                       // 71168
    cudaFuncSetAttribute(edge_fused_kernel,
                         cudaFuncAttributeMaxDynamicSharedMemorySize, edgeSmem);

    // ---- weight prep ----
    prep_gat<<<32, 256>>>(gb_Wl, gb_Wr, gr_Wl, gr_Wr, WH, WL);
    prep_cg<<<16, 256>>>(cl_Wf, cl_Ws, cr_Wf, cr_Ws, WH, WL);
    prep_misc<<<3, 256>>>(W_enc, node_W, WH, WL);

    const int MT = NNODE / 128;   // 160

    auto gemm = [&](const float* A, size_t woff, const float* ba, const float* bb,
                    float* C, int K, int Ntot) {
        dim3 grid(MT, Ntot / 128);
        const int smem = 4 * 128 * (K + 8) * 2;
        gemm_v3_kernel<<<grid, 512, smem>>>(A, WH + woff, WL + woff, ba, bb, C, K, Ntot);
    };

    // encoder
    gemm(x_my,  0, b_enc, nullptr, XM, CDm, Hd);
    gemm(x_opp, 0, b_enc, nullptr, XO, CDm, Hd);

    for (int l = 0; l < 2; l++) {
        const size_t L = LOFF(l);
        const size_t WLB = L, WRB = L + 4*TSZ, WLR = L + 8*TSZ, WRR = L + 12*TSZ;
        const size_t CLD = L + 16*TSZ, CLS = L + 18*TSZ;
        const size_t CRD = L + 20*TSZ, CRS = L + 22*TSZ;
        const size_t NW  = L + 24*TSZ;
        const float* att_b = gb_att + l*4*Hd;
        const float* att_r = gr_att + l*4*Hd;
        const float* bb = gb_b + l*Hd;
        const float* br = gr_b + l*Hd;
        const float* clbf = cl_bf + l*Hd;  const float* clbs = cl_bs + l*Hd;
        const float* crbf = cr_bf + l*Hd;  const float* crbs = cr_bs + l*Hd;
        const float* nb = node_b + l*Hd;

        // ---- new_xo = gat_beats(xm->xo) + cg_loses(xm->xo) ----
        gemm(XM, WLB, nullptr, nullptr, XL, Hd, 512);
        gemm(XO, WRB, nullptr, nullptr, XR, Hd, 512);
        gemm(XO, CLD, clbf, clbs, FDSD, Hd, 256);
        gemm(XM, CLS, nullptr, nullptr, FSSS, Hd, 256);
        edge_fused_kernel<<<NG, 256, edgeSmem>>>(XL, XR, att_b, bb, FDSD, FSSS, XO, NO);

        // ---- new_xm = cg_rev(xo->xm) + gat_rev(xo->xm) ----
        gemm(XO, WLR, nullptr, nullptr, XL, Hd, 512);
        gemm(XM, WRR, nullptr, nullptr, XR, Hd, 512);
        gemm(XM, CRD, crbf, crbs, FDSD, Hd, 256);
        gemm(XO, CRS, nullptr, nullptr, FSSS, Hd, 256);
        edge_fused_kernel<<<NG, 256, edgeSmem>>>(XL, XR, att_r, br, FDSD, FSSS, XM, NM);

        // ---- node linear ----
        gemm(NM, NW, nb, nullptr, XM, Hd, Hd);
        gemm(NO, NW, nb, nullptr, XO, Hd, Hd);
    }

    head_kernel<<<NG, 128>>>(XM, XO, W1, b1, W2, b2, (float*)d_out);
}

// round 14
// speedup vs baseline: 1.6984x; 1.2245x over previous
#include <cuda_runtime.h>
#include <cuda_bf16.h>
#include <cstdint>

typedef unsigned long long u64;
typedef __nv_bfloat16 bf16;

// ============================================================================
// Round 14 (= round 13 resubmit after infra failure): batched-job HMMA GEMM
// (M-tile 64, 256thr, 2 blocks/SM) + fused both-direction edge kernel.
// 11 launches total.
// ============================================================================

namespace {
constexpr int NNODE = 20480;
constexpr int NG    = 2048;
constexpr int Hd    = 128;
constexpr int CDm   = 32;
constexpr size_t TSZ = 16384;
constexpr size_t ENC_SZ = 4096;
constexpr size_t LAYER_TILES = 25;
constexpr size_t WBUF_SZ = ENC_SZ + 2*LAYER_TILES*TSZ;
}

__host__ __device__ inline size_t LOFF(int l) { return ENC_SZ + (size_t)l*LAYER_TILES*TSZ; }

// -------- global scratch --------
__device__ float g_XM[NNODE*Hd];
__device__ float g_XO[NNODE*Hd];
__device__ float g_NM[NNODE*Hd];
__device__ float g_NO[NNODE*Hd];
__device__ float g_XL[NNODE*512];
__device__ float g_XR[NNODE*512];
__device__ float g_XL2[NNODE*512];
__device__ float g_XR2[NNODE*512];
__device__ float g_FDSD[NNODE*256];
__device__ float g_FSSS[NNODE*256];
__device__ float g_FDSD2[NNODE*256];
__device__ float g_FSSS2[NNODE*256];
__device__ bf16  g_Whi[WBUF_SZ];
__device__ bf16  g_Wlo[WBUF_SZ];

struct Job {
    const float* A;       // activation [NNODE, K] fp32
    long long    woff;    // offset into prepped weight buffers (128xK tile)
    const float* bias;    // nullptr or 128-entry bias
    float*       C;       // output
    int          cstride; // C row stride
    int          col0;    // C column offset
};
struct JobBatch { Job j[24]; };

__device__ __forceinline__ void mma16816(float* d, const uint32_t* a,
                                         uint32_t b0, uint32_t b1) {
    asm volatile(
        "mma.sync.aligned.m16n8k16.row.col.f32.bf16.bf16.f32 "
        "{%0,%1,%2,%3}, {%4,%5,%6,%7}, {%8,%9}, {%0,%1,%2,%3};"
        : "+f"(d[0]), "+f"(d[1]), "+f"(d[2]), "+f"(d[3])
        : "r"(a[0]), "r"(a[1]), "r"(a[2]), "r"(a[3]), "r"(b0), "r"(b1));
}

#define LDSM4(r, addr) \
    asm volatile("ldmatrix.sync.aligned.m8n8.x4.shared.b16 {%0,%1,%2,%3}, [%4];" \
                 : "=r"((r)[0]), "=r"((r)[1]), "=r"((r)[2]), "=r"((r)[3]) \
                 : "r"(addr))

// ============================================================================
// Weight prep (validated round 12, unchanged layout)
// ============================================================================
extern "C" __global__ void __launch_bounds__(256)
prep_gat(const float* __restrict__ gbWl, const float* __restrict__ gbWr,
         const float* __restrict__ grWl, const float* __restrict__ grWr,
         bf16* __restrict__ hi, bf16* __restrict__ lo)
{
    const int b = blockIdx.x;                 // 32
    const int l = b >> 4, tq = (b >> 2) & 3, tile = b & 3;
    const float* src;
    if      (tq == 0) src = gbWl;
    else if (tq == 1) src = gbWr;
    else if (tq == 2) src = grWl;
    else              src = grWr;
    src += (size_t)l * 128 * 512;
    const size_t dst = LOFF(l) + (size_t)tq*4*TSZ + (size_t)tile*TSZ;
    for (int idx = threadIdx.x; idx < 16384; idx += 256) {
        const int nl = idx >> 7, k = idx & 127;
        const float w = src[k*512 + tile*128 + nl];
        const bf16 h = __float2bfloat16(w);
        hi[dst + nl*128 + k] = h;
        lo[dst + nl*128 + k] = __float2bfloat16(w - __bfloat162float(h));
    }
}

extern "C" __global__ void __launch_bounds__(256)
prep_cg(const float* __restrict__ clWf, const float* __restrict__ clWs,
        const float* __restrict__ crWf, const float* __restrict__ crWs,
        bf16* __restrict__ hi, bf16* __restrict__ lo)
{
    const int b = blockIdx.x;                 // 16
    const int l = b >> 3, q = b & 7;
    const int buf = q >> 1, tile = q & 1;
    const float* fw = (buf < 2) ? clWf : crWf;
    const float* sw = (buf < 2) ? clWs : crWs;
    const float* src = (tile ? sw : fw) + (size_t)l*256*128 + ((buf & 1) ? 128*128 : 0);
    const size_t dst = LOFF(l) + (size_t)(16 + buf*2 + tile)*TSZ;
    for (int idx = threadIdx.x; idx < 16384; idx += 256) {
        const int nl = idx >> 7, k = idx & 127;
        const float w = src[k*128 + nl];
        const bf16 h = __float2bfloat16(w);
        hi[dst + nl*128 + k] = h;
        lo[dst + nl*128 + k] = __float2bfloat16(w - __bfloat162float(h));
    }
}

extern "C" __global__ void __launch_bounds__(256)
prep_misc(const float* __restrict__ Wenc, const float* __restrict__ nodeW,
          bf16* __restrict__ hi, bf16* __restrict__ lo)
{
    const int b = blockIdx.x;                 // 3
    if (b == 0) {
        for (int idx = threadIdx.x; idx < 4096; idx += 256) {
            const int nl = idx >> 5, k = idx & 31;
            const float w = Wenc[k*128 + nl];
            const bf16 h = __float2bfloat16(w);
            hi[nl*32 + k] = h;
            lo[nl*32 + k] = __float2bfloat16(w - __bfloat162float(h));
        }
    } else {
        const int l = b - 1;
        const float* src = nodeW + (size_t)l*128*128;
        const size_t dst = LOFF(l) + 24*TSZ;
        for (int idx = threadIdx.x; idx < 16384; idx += 256) {
            const int nl = idx >> 7, k = idx & 127;
            const float w = src[k*128 + nl];
            const bf16 h = __float2bfloat16(w);
            hi[dst + nl*128 + k] = h;
            lo[dst + nl*128 + k] = __float2bfloat16(w - __bfloat162float(h));
        }
    }
}

// ============================================================================
// Batched GEMM: blockIdx.x = m-tile (64 rows), blockIdx.y = job.
// C[m0:m0+64, col0:col0+128] = A[:,K] @ Wtile (+bias). Split-bf16 3-term.
// smem: (2*64 + 2*128) * (K+8) * 2 bytes. 256 threads, 8 warps = 2(M) x 4(N).
// ============================================================================
extern "C" __global__ void __launch_bounds__(256, 2)
gemm_batch_kernel(JobBatch jb,
                  const bf16* __restrict__ WHbase, const bf16* __restrict__ WLbase,
                  int K)
{
    const Job J = jb.j[blockIdx.y];
    extern __shared__ __align__(16) char smem_raw[];
    bf16* s = (bf16*)smem_raw;
    const int KP = K + 8;
    bf16* Ah = s;
    bf16* Al = s +  64*KP;
    bf16* Bh = s + 128*KP;
    bf16* Bl = s + 256*KP;

    const int t  = threadIdx.x;
    const int m0 = blockIdx.x * 64;

    // ---- stage A tile [64, K] fp32 -> hi/lo ----
    for (int idx = t; idx < 64*K; idx += 256) {
        const int r = idx / K, k = idx - r*K;
        const float a = J.A[(size_t)(m0 + r)*K + k];
        const bf16 hv = __float2bfloat16(a);
        Ah[r*KP + k] = hv;
        Al[r*KP + k] = __float2bfloat16(a - __bfloat162float(hv));
    }
    // ---- stage B tile [128, K] from prepped bf16 ----
    {
        const bf16* wh = WHbase + J.woff;
        const bf16* wl = WLbase + J.woff;
        const int c8n = K >> 3;
        for (int idx = t; idx < 128*c8n; idx += 256) {
            const int row = idx / c8n, c8 = idx - row*c8n;
            *(uint4*)&Bh[row*KP + c8*8] = ((const uint4*)(wh + (size_t)row*K))[c8];
            *(uint4*)&Bl[row*KP + c8*8] = ((const uint4*)(wl + (size_t)row*K))[c8];
        }
    }
    __syncthreads();

    const int wid = t >> 5, lane = t & 31;
    const int wm = wid & 1, wn = wid >> 1;     // 2 (M) x 4 (N) warps
    const int gID = lane >> 2, tig = lane & 3;

    const uint32_t laneOff = (uint32_t)(((lane & 15)*KP + (lane >> 4)*8) * 2);
    const uint32_t aHiB = (uint32_t)__cvta_generic_to_shared(Ah) + (uint32_t)(wm*32*KP*2) + laneOff;
    const uint32_t aLoB = (uint32_t)__cvta_generic_to_shared(Al) + (uint32_t)(wm*32*KP*2) + laneOff;
    const uint32_t bHiB = (uint32_t)__cvta_generic_to_shared(Bh) + (uint32_t)(wn*32*KP*2) + laneOff;
    const uint32_t bLoB = (uint32_t)__cvta_generic_to_shared(Bl) + (uint32_t)(wn*32*KP*2) + laneOff;
    const uint32_t mtOff = (uint32_t)(16*KP*2);

    float acc[2][4][4];
#pragma unroll
    for (int mt = 0; mt < 2; mt++)
#pragma unroll
        for (int nt = 0; nt < 4; nt++)
#pragma unroll
            for (int q = 0; q < 4; q++) acc[mt][nt][q] = 0.f;

    const int KS = K >> 4;
#pragma unroll 1
    for (int ks = 0; ks < KS; ks++) {
        const uint32_t ko = (uint32_t)(ks * 32);
        uint32_t ah[2][4], al[2][4], b0h[4], b1h[4], b0l[4], b1l[4];
        LDSM4(ah[0], aHiB + ko);
        LDSM4(ah[1], aHiB + mtOff + ko);
        LDSM4(al[0], aLoB + ko);
        LDSM4(al[1], aLoB + mtOff + ko);
        LDSM4(b0h, bHiB + ko);
        LDSM4(b1h, bHiB + mtOff + ko);
        LDSM4(b0l, bLoB + ko);
        LDSM4(b1l, bLoB + mtOff + ko);
#pragma unroll
        for (int mt = 0; mt < 2; mt++) {
            mma16816(acc[mt][0], ah[mt], b0h[0], b0h[2]);
            mma16816(acc[mt][0], ah[mt], b0l[0], b0l[2]);
            mma16816(acc[mt][0], al[mt], b0h[0], b0h[2]);
            mma16816(acc[mt][1], ah[mt], b0h[1], b0h[3]);
            mma16816(acc[mt][1], ah[mt], b0l[1], b0l[3]);
            mma16816(acc[mt][1], al[mt], b0h[1], b0h[3]);
            mma16816(acc[mt][2], ah[mt], b1h[0], b1h[2]);
            mma16816(acc[mt][2], ah[mt], b1l[0], b1l[2]);
            mma16816(acc[mt][2], al[mt], b1h[0], b1h[2]);
            mma16816(acc[mt][3], ah[mt], b1h[1], b1h[3]);
            mma16816(acc[mt][3], ah[mt], b1l[1], b1l[3]);
            mma16816(acc[mt][3], al[mt], b1h[1], b1h[3]);
        }
    }

    // ---- epilogue: bias indexed by LOCAL column (all jobs use 128-entry bias)
#pragma unroll
    for (int mt = 0; mt < 2; mt++) {
        const int row = m0 + wm*32 + mt*16 + gID;
#pragma unroll
        for (int nt = 0; nt < 4; nt++) {
            const int cl = wn*32 + nt*8 + 2*tig;    // local col 0..127
            float2 v0 = make_float2(acc[mt][nt][0], acc[mt][nt][1]);
            float2 v1 = make_float2(acc[mt][nt][2], acc[mt][nt][3]);
            if (J.bias) {
                const float2 bb = *(const float2*)&J.bias[cl];
                v0.x += bb.x; v0.y += bb.y;
                v1.x += bb.x; v1.y += bb.y;
            }
            const int col = J.col0 + cl;
            *(float2*)&J.C[(size_t)row*J.cstride + col]       = v0;
            *(float2*)&J.C[(size_t)(row + 8)*J.cstride + col] = v1;
        }
    }
}

// ============================================================================
// Fused edge kernel, BOTH directions: dir = blockIdx.x >> 11.
// OUT = GATv2(XL,XR,att)+gbias + CGConv(FDSD,FSSS)+Xd
// ============================================================================
extern "C" __global__ void __launch_bounds__(256)
edge2_kernel(const float* __restrict__ XLa, const float* __restrict__ XRa,
             const float* __restrict__ XLb, const float* __restrict__ XRb,
             const float* __restrict__ attA, const float* __restrict__ attB,
             const float* __restrict__ biasA, const float* __restrict__ biasB,
             const float* __restrict__ FDa, const float* __restrict__ FSa,
             const float* __restrict__ FDb, const float* __restrict__ FSb,
             const float* __restrict__ XdA, const float* __restrict__ XdB,
             float* __restrict__ OUTa, float* __restrict__ OUTb)
{
    extern __shared__ float sm[];
    float* sXL  = sm;            // 5120
    float* sXR  = sm + 5120;     // 5120
    float* sFd  = sm + 10240;    // 1280
    float* sFs  = sm + 11520;
    float* sSd  = sm + 12800;
    float* sSs  = sm + 14080;
    float* sXd  = sm + 15360;    // 1280
    float* sLog = sm + 16640;    // 640
    float* sAtt = sm + 17280;    // 512

    const int dir = blockIdx.x >> 11;
    const int g = blockIdx.x & 2047;
    const int t = threadIdx.x;
    const int wid = t >> 5, lane = t & 31;

    const float* XL   = dir ? XLb : XLa;
    const float* XR   = dir ? XRb : XRa;
    const float* att  = dir ? attB : attA;
    const float* gbias= dir ? biasB : biasA;
    const float* FDSD = dir ? FDb : FDa;
    const float* FSSS = dir ? FSb : FSa;
    const float* Xd   = dir ? XdB : XdA;
    float* OUT        = dir ? OUTb : OUTa;

    const size_t base = (size_t)g * 5120;
    for (int idx = t; idx < 5120; idx += 256) {
        sXL[idx] = XL[base + idx];
        sXR[idx] = XR[base + idx];
    }
    for (int idx = t; idx < 1280; idx += 256) {
        const int i = idx >> 7, c = idx & 127;
        const size_t b2 = (size_t)(g*10 + i)*256 + c;
        sFd[idx] = FDSD[b2];  sSd[idx] = FDSD[b2 + 128];
        sFs[idx] = FSSS[b2];  sSs[idx] = FSSS[b2 + 128];
        sXd[idx] = Xd[(size_t)(g*10 + i)*128 + c];
    }
    for (int idx = t; idx < 512; idx += 256) sAtt[idx] = att[idx];
    __syncthreads();

#pragma unroll 1
    for (int pp = 0; pp < 5; pp++) {
        const int p = wid + pp * 8;
        const int h = p / 10, j = p % 10;
        const float4 xr = *(const float4*)&sXR[j*512 + h*128 + lane*4];
        const float4 at = *(const float4*)&sAtt[h*128 + lane*4];
#pragma unroll
        for (int i = 0; i < 10; i++) {
            const float4 xl = *(const float4*)&sXL[i*512 + h*128 + lane*4];
            float e, sv;
            e = xl.x + xr.x; sv = at.x * fmaf(e, 0.6f, 0.4f*fabsf(e));
            e = xl.y + xr.y; sv = fmaf(at.y, fmaf(e, 0.6f, 0.4f*fabsf(e)), sv);
            e = xl.z + xr.z; sv = fmaf(at.z, fmaf(e, 0.6f, 0.4f*fabsf(e)), sv);
            e = xl.w + xr.w; sv = fmaf(at.w, fmaf(e, 0.6f, 0.4f*fabsf(e)), sv);
#pragma unroll
            for (int o = 16; o > 0; o >>= 1) sv += __shfl_xor_sync(0xffffffffu, sv, o);
            if (lane == 0) sLog[p*16 + i] = sv;
        }
    }
    __syncthreads();

    if (t < 40) {
        float* lg = sLog + t*16;
        float m = lg[0];
#pragma unroll
        for (int i = 1; i < 10; i++) m = fmaxf(m, lg[i]);
        float a[10]; float sum = 0.f;
#pragma unroll
        for (int i = 0; i < 10; i++) { a[i] = __expf(lg[i] - m); sum += a[i]; }
        const float inv = __fdividef(1.f, sum);
#pragma unroll
        for (int i = 0; i < 10; i++) lg[i] = a[i] * inv;
    }
    __syncthreads();

    {
        const int c = t & 127, rh = t >> 7;
        float accj[5] = {0.f, 0.f, 0.f, 0.f, 0.f};
#pragma unroll
        for (int h = 0; h < 4; h++) {
            float xlh[10];
#pragma unroll
            for (int i = 0; i < 10; i++) xlh[i] = sXL[i*512 + h*128 + c];
#pragma unroll
            for (int jj = 0; jj < 5; jj++) {
                const float* al = sLog + (h*10 + rh*5 + jj)*16;
                float v = accj[jj];
#pragma unroll
                for (int i = 0; i < 10; i++) v = fmaf(al[i], xlh[i], v);
                accj[jj] = v;
            }
        }
        const float bv = gbias[c];
#pragma unroll
        for (int jj = 0; jj < 5; jj++) {
            const int i = rh*5 + jj;
            const float fd = sFd[i*128 + c];
            const float sd = sSd[i*128 + c];
            float cg = sXd[i*128 + c];
#pragma unroll
            for (int j = 0; j < 10; j++) {
                const float f = fd + sFs[j*128 + c];
                const float s2 = sd + sSs[j*128 + c];
                const float sig = __fdividef(1.f, 1.f + __expf(-f));
                const float sp  = fmaxf(s2, 0.f) + __logf(1.f + __expf(-fabsf(s2)));
                cg = fmaf(sig, sp, cg);
            }
            OUT[(size_t)(g*10 + i)*128 + c] = accj[jj]*0.25f + bv + cg;
        }
    }
}

// ============================================================================
// Head (validated)
// ============================================================================
extern "C" __global__ void __launch_bounds__(128)
head_kernel(const float* __restrict__ XM, const float* __restrict__ XO,
            const float* __restrict__ W1, const float* __restrict__ b1,
            const float* __restrict__ W2, const float* __restrict__ b2,
            float* __restrict__ out)
{
    __shared__ float pool[256], red[128];
    const int g = blockIdx.x, t = threadIdx.x;
    {
        float pm = 0.f, po = 0.f;
#pragma unroll
        for (int r = 0; r < 10; r++) {
            pm += XM[(size_t)(g*10 + r)*128 + t];
            po += XO[(size_t)(g*10 + r)*128 + t];
        }
        pool[t] = pm * 0.1f;
        pool[128 + t] = po * 0.1f;
    }
    __syncthreads();
    {
        float a = 0.f;
#pragma unroll 4
        for (int k = 0; k < 256; k++) a = fmaf(pool[k], W1[k*128 + t], a);
        a += b1[t];
        a = (a >= 0.f) ? a : 128.f * a;
        red[t] = a * W2[t];
    }
    __syncthreads();
    if (t < 32) {
        float v = red[t] + red[t+32] + red[t+64] + red[t+96];
#pragma unroll
        for (int o = 16; o > 0; o >>= 1) v += __shfl_xor_sync(0xffffffffu, v, o);
        if (t == 0) out[g] = v + b2[0];
    }
}

// ============================================================================
// Host launcher
// ============================================================================
extern "C" void kernel_launch(void* const* d_in, const int* in_sizes, int n_in,
                              void* d_out, int out_size)
{
    const float* x_my   = (const float*)d_in[0];
    const float* x_opp  = (const float*)d_in[1];
    const float* W_enc  = (const float*)d_in[2];
    const float* b_enc  = (const float*)d_in[3];
    const float* gb_Wl  = (const float*)d_in[4];
    const float* gb_Wr  = (const float*)d_in[5];
    const float* gb_att = (const float*)d_in[6];
    const float* gb_b   = (const float*)d_in[7];
    const float* gr_Wl  = (const float*)d_in[8];
    const float* gr_Wr  = (const float*)d_in[9];
    const float* gr_att = (const float*)d_in[10];
    const float* gr_b   = (const float*)d_in[11];
    const float* cl_Wf  = (const float*)d_in[12];
    const float* cl_bf  = (const float*)d_in[13];
    const float* cl_Ws  = (const float*)d_in[14];
    const float* cl_bs  = (const float*)d_in[15];
    const float* cr_Wf  = (const float*)d_in[16];
    const float* cr_bf  = (const float*)d_in[17];
    const float* cr_Ws  = (const float*)d_in[18];
    const float* cr_bs  = (const float*)d_in[19];
    const float* node_W = (const float*)d_in[20];
    const float* node_b = (const float*)d_in[21];
    const float* W1     = (const float*)d_in[22];
    const float* b1     = (const float*)d_in[23];
    const float* W2     = (const float*)d_in[24];
    const float* b2     = (const float*)d_in[25];

    float *XM, *XO, *NM, *NO, *XL, *XR, *XL2, *XR2, *FDSD, *FSSS, *FDSD2, *FSSS2;
    bf16 *WH, *WL;
    cudaGetSymbolAddress((void**)&XM, g_XM);
    cudaGetSymbolAddress((void**)&XO, g_XO);
    cudaGetSymbolAddress((void**)&NM, g_NM);
    cudaGetSymbolAddress((void**)&NO, g_NO);
    cudaGetSymbolAddress((void**)&XL, g_XL);
    cudaGetSymbolAddress((void**)&XR, g_XR);
    cudaGetSymbolAddress((void**)&XL2, g_XL2);
    cudaGetSymbolAddress((void**)&XR2, g_XR2);
    cudaGetSymbolAddress((void**)&FDSD, g_FDSD);
    cudaGetSymbolAddress((void**)&FSSS, g_FSSS);
    cudaGetSymbolAddress((void**)&FDSD2, g_FDSD2);
    cudaGetSymbolAddress((void**)&FSSS2, g_FSSS2);
    cudaGetSymbolAddress((void**)&WH, g_Whi);
    cudaGetSymbolAddress((void**)&WL, g_Wlo);

    const int gemmSmemMax = (2*64 + 2*128) * (Hd + 8) * 2;   // 104448
    cudaFuncSetAttribute(gemm_batch_kernel,
                         cudaFuncAttributeMaxDynamicSharedMemorySize, gemmSmemMax);
    const int edgeSmem = 17792 * 4;
    cudaFuncSetAttribute(edge2_kernel,
                         cudaFuncAttributeMaxDynamicSharedMemorySize, edgeSmem);

    // ---- weight prep ----
    prep_gat<<<32, 256>>>(gb_Wl, gb_Wr, gr_Wl, gr_Wr, WH, WL);
    prep_cg<<<16, 256>>>(cl_Wf, cl_Ws, cr_Wf, cr_Ws, WH, WL);
    prep_misc<<<3, 256>>>(W_enc, node_W, WH, WL);

    const int MT = NNODE / 64;   // 320 m-tiles

    auto launch_batch = [&](const JobBatch& jb, int njobs, int K) {
        const int smem = (2*64 + 2*128) * (K + 8) * 2;
        dim3 grid(MT, njobs);
        gemm_batch_kernel<<<grid, 256, smem>>>(jb, WH, WL, K);
    };

    // ---- encoder batch (K=32, 2 jobs) ----
    {
        JobBatch jb{};
        jb.j[0] = { x_my,  0, b_enc, XM, Hd, 0 };
        jb.j[1] = { x_opp, 0, b_enc, XO, Hd, 0 };
        launch_batch(jb, 2, CDm);
    }

    for (int l = 0; l < 2; l++) {
        const long long L = (long long)LOFF(l);
        const long long WLB = L, WRB = L + 4*(long long)TSZ;
        const long long WLR = L + 8*(long long)TSZ, WRR = L + 12*(long long)TSZ;
        const long long CLD = L + 16*(long long)TSZ, CLS = L + 18*(long long)TSZ;
        const long long CRD = L + 20*(long long)TSZ, CRS = L + 22*(long long)TSZ;
        const long long NW  = L + 24*(long long)TSZ;
        const float* att_b = gb_att + l*4*Hd;
        const float* att_r = gr_att + l*4*Hd;
        const float* bb = gb_b + l*Hd;
        const float* br = gr_b + l*Hd;
        const float* clbf = cl_bf + l*Hd;  const float* clbs = cl_bs + l*Hd;
        const float* crbf = cr_bf + l*Hd;  const float* crbs = cr_bs + l*Hd;
        const float* nb = node_b + l*Hd;

        // ---- phase GEMM batch: 24 jobs, both directions ----
        {
            JobBatch jb{};
            int n = 0;
            for (int tile = 0; tile < 4; tile++)
                jb.j[n++] = { XM, WLB + tile*(long long)TSZ, nullptr, XL, 512, tile*128 };
            for (int tile = 0; tile < 4; tile++)
                jb.j[n++] = { XO, WRB + tile*(long long)TSZ, nullptr, XR, 512, tile*128 };
            jb.j[n++] = { XO, CLD,                 clbf, FDSD, 256, 0   };
            jb.j[n++] = { XO, CLD + (long long)TSZ, clbs, FDSD, 256, 128 };
            jb.j[n++] = { XM, CLS,                 nullptr, FSSS, 256, 0   };
            jb.j[n++] = { XM, CLS + (long long)TSZ, nullptr, FSSS, 256, 128 };
            for (int tile = 0; tile < 4; tile++)
                jb.j[n++] = { XO, WLR + tile*(long long)TSZ, nullptr, XL2, 512, tile*128 };
            for (int tile = 0; tile < 4; tile++)
                jb.j[n++] = { XM, WRR + tile*(long long)TSZ, nullptr, XR2, 512, tile*128 };
            jb.j[n++] = { XM, CRD,                 crbf, FDSD2, 256, 0   };
            jb.j[n++] = { XM, CRD + (long long)TSZ, crbs, FDSD2, 256, 128 };
            jb.j[n++] = { XO, CRS,                 nullptr, FSSS2, 256, 0   };
            jb.j[n++] = { XO, CRS + (long long)TSZ, nullptr, FSSS2, 256, 128 };
            launch_batch(jb, 24, Hd);
        }

        // ---- edges, both directions in one launch ----
        edge2_kernel<<<2*NG, 256, edgeSmem>>>(
            XL, XR, XL2, XR2, att_b, att_r, bb, br,
            FDSD, FSSS, FDSD2, FSSS2, XO, XM, NO, NM);

        // ---- node linear batch (2 jobs) ----
        {
            JobBatch jb{};
            jb.j[0] = { NM, NW, nb, XM, Hd, 0 };
            jb.j[1] = { NO, NW, nb, XO, Hd, 0 };
            launch_batch(jb, 2, Hd);
        }
    }

    head_kernel<<<NG, 128>>>(XM, XO, W1, b1, W2, b2, (float*)d_out);
}

// round 15
// speedup vs baseline: 1.9517x; 1.1491x over previous
#include <cuda_runtime.h>
#include <cuda_bf16.h>
#include <cstdint>

typedef unsigned long long u64;
typedef __nv_bfloat16 bf16;
typedef __nv_bfloat162 bf162;

// ============================================================================
// Round 15: batched HMMA GEMM with split-bf16 activation storage (staging is
// pure uint4 copy) + double-buffered ldmatrix k-loop. 14 launches.
// ============================================================================

namespace {
constexpr int NNODE = 20480;
constexpr int NG    = 2048;
constexpr int Hd    = 128;
constexpr int CDm   = 32;
constexpr size_t TSZ = 16384;
constexpr size_t ENC_SZ = 4096;
constexpr size_t LAYER_TILES = 25;
constexpr size_t WBUF_SZ = ENC_SZ + 2*LAYER_TILES*TSZ;
}

__host__ __device__ inline size_t LOFF(int l) { return ENC_SZ + (size_t)l*LAYER_TILES*TSZ; }

// -------- global scratch --------
__device__ bf16  g_XMh[NNODE*Hd];  __device__ bf16 g_XMl[NNODE*Hd];
__device__ bf16  g_XOh[NNODE*Hd];  __device__ bf16 g_XOl[NNODE*Hd];
__device__ bf16  g_NMh[NNODE*Hd];  __device__ bf16 g_NMl[NNODE*Hd];
__device__ bf16  g_NOh[NNODE*Hd];  __device__ bf16 g_NOl[NNODE*Hd];
__device__ bf16  g_XAh[2*NNODE*CDm]; __device__ bf16 g_XAl[2*NNODE*CDm];
__device__ float g_XL[NNODE*512];
__device__ float g_XR[NNODE*512];
__device__ float g_XL2[NNODE*512];
__device__ float g_XR2[NNODE*512];
__device__ float g_FDSD[NNODE*256];
__device__ float g_FSSS[NNODE*256];
__device__ float g_FDSD2[NNODE*256];
__device__ float g_FSSS2[NNODE*256];
__device__ bf16  g_Whi[WBUF_SZ];
__device__ bf16  g_Wlo[WBUF_SZ];

struct Job {
    const bf16* Ahi;      // activation hi [NNODE, K]
    const bf16* Alo;      // activation lo
    long long    woff;    // prepped weight tile offset
    const float* bias;    // nullptr or 128-entry bias
    float*       Cf;      // fp32 output (nullptr if split output)
    bf16*        Chi;     // split bf16 output hi (nullptr if fp32)
    bf16*        Clo;
    int          cstride;
    int          col0;
};
struct JobBatch { Job j[24]; };

__device__ __forceinline__ void mma16816(float* d, const uint32_t* a,
                                         uint32_t b0, uint32_t b1) {
    asm volatile(
        "mma.sync.aligned.m16n8k16.row.col.f32.bf16.bf16.f32 "
        "{%0,%1,%2,%3}, {%4,%5,%6,%7}, {%8,%9}, {%0,%1,%2,%3};"
        : "+f"(d[0]), "+f"(d[1]), "+f"(d[2]), "+f"(d[3])
        : "r"(a[0]), "r"(a[1]), "r"(a[2]), "r"(a[3]), "r"(b0), "r"(b1));
}

#define LDSM4(r, addr) \
    asm volatile("ldmatrix.sync.aligned.m8n8.x4.shared.b16 {%0,%1,%2,%3}, [%4];" \
                 : "=r"((r)[0]), "=r"((r)[1]), "=r"((r)[2]), "=r"((r)[3]) \
                 : "r"(addr))

// ============================================================================
// Weight prep (validated) + activation-input prep
// ============================================================================
extern "C" __global__ void __launch_bounds__(256)
prep_gat(const float* __restrict__ gbWl, const float* __restrict__ gbWr,
         const float* __restrict__ grWl, const float* __restrict__ grWr,
         bf16* __restrict__ hi, bf16* __restrict__ lo)
{
    const int b = blockIdx.x;                 // 32
    const int l = b >> 4, tq = (b >> 2) & 3, tile = b & 3;
    const float* src;
    if      (tq == 0) src = gbWl;
    else if (tq == 1) src = gbWr;
    else if (tq == 2) src = grWl;
    else              src = grWr;
    src += (size_t)l * 128 * 512;
    const size_t dst = LOFF(l) + (size_t)tq*4*TSZ + (size_t)tile*TSZ;
    for (int idx = threadIdx.x; idx < 16384; idx += 256) {
        const int nl = idx >> 7, k = idx & 127;
        const float w = src[k*512 + tile*128 + nl];
        const bf16 h = __float2bfloat16(w);
        hi[dst + nl*128 + k] = h;
        lo[dst + nl*128 + k] = __float2bfloat16(w - __bfloat162float(h));
    }
}

extern "C" __global__ void __launch_bounds__(256)
prep_cg(const float* __restrict__ clWf, const float* __restrict__ clWs,
        const float* __restrict__ crWf, const float* __restrict__ crWs,
        bf16* __restrict__ hi, bf16* __restrict__ lo)
{
    const int b = blockIdx.x;                 // 16
    const int l = b >> 3, q = b & 7;
    const int buf = q >> 1, tile = q & 1;
    const float* fw = (buf < 2) ? clWf : crWf;
    const float* sw = (buf < 2) ? clWs : crWs;
    const float* src = (tile ? sw : fw) + (size_t)l*256*128 + ((buf & 1) ? 128*128 : 0);
    const size_t dst = LOFF(l) + (size_t)(16 + buf*2 + tile)*TSZ;
    for (int idx = threadIdx.x; idx < 16384; idx += 256) {
        const int nl = idx >> 7, k = idx & 127;
        const float w = src[k*128 + nl];
        const bf16 h = __float2bfloat16(w);
        hi[dst + nl*128 + k] = h;
        lo[dst + nl*128 + k] = __float2bfloat16(w - __bfloat162float(h));
    }
}

extern "C" __global__ void __launch_bounds__(256)
prep_misc(const float* __restrict__ Wenc, const float* __restrict__ nodeW,
          const float* __restrict__ xmy, const float* __restrict__ xopp,
          bf16* __restrict__ hi, bf16* __restrict__ lo,
          bf16* __restrict__ XAh, bf16* __restrict__ XAl)
{
    const int b = blockIdx.x;                 // 3 + 40
    if (b == 0) {
        for (int idx = threadIdx.x; idx < 4096; idx += 256) {
            const int nl = idx >> 5, k = idx & 31;
            const float w = Wenc[k*128 + nl];
            const bf16 h = __float2bfloat16(w);
            hi[nl*32 + k] = h;
            lo[nl*32 + k] = __float2bfloat16(w - __bfloat162float(h));
        }
    } else if (b <= 2) {
        const int l = b - 1;
        const float* src = nodeW + (size_t)l*128*128;
        const size_t dst = LOFF(l) + 24*TSZ;
        for (int idx = threadIdx.x; idx < 16384; idx += 256) {
            const int nl = idx >> 7, k = idx & 127;
            const float w = src[k*128 + nl];
            const bf16 h = __float2bfloat16(w);
            hi[dst + nl*128 + k] = h;
            lo[dst + nl*128 + k] = __float2bfloat16(w - __bfloat162float(h));
        }
    } else {
        // x conversion: 2*NNODE*32 = 1310720 elems over 40 blocks
        const size_t chunk = 32768;
        const size_t base = (size_t)(b - 3) * chunk;
        for (size_t idx = base + threadIdx.x; idx < base + chunk; idx += 256) {
            const float v = (idx < (size_t)NNODE*CDm)
                          ? xmy[idx] : xopp[idx - (size_t)NNODE*CDm];
            const bf16 h = __float2bfloat16(v);
            XAh[idx] = h;
            XAl[idx] = __float2bfloat16(v - __bfloat162float(h));
        }
    }
}

// ============================================================================
// Batched GEMM, double-buffered k-loop, split-bf16 activations.
// ============================================================================
extern "C" __global__ void __launch_bounds__(256, 2)
gemm_batch_kernel(JobBatch jb,
                  const bf16* __restrict__ WHbase, const bf16* __restrict__ WLbase,
                  int K)
{
    const Job J = jb.j[blockIdx.y];
    extern __shared__ __align__(16) char smem_raw[];
    bf16* s = (bf16*)smem_raw;
    const int KP = K + 8;
    bf16* Ah = s;
    bf16* Al = s +  64*KP;
    bf16* Bh = s + 128*KP;
    bf16* Bl = s + 256*KP;

    const int t  = threadIdx.x;
    const int m0 = blockIdx.x * 64;

    // ---- stage A tile [64, K]: pure uint4 copy from split storage ----
    {
        const int c8n = K >> 3;
        for (int idx = t; idx < 64*c8n; idx += 256) {
            const int row = idx / c8n, c8 = idx - row*c8n;
            *(uint4*)&Ah[row*KP + c8*8] = ((const uint4*)(J.Ahi + (size_t)(m0+row)*K))[c8];
            *(uint4*)&Al[row*KP + c8*8] = ((const uint4*)(J.Alo + (size_t)(m0+row)*K))[c8];
        }
    }
    // ---- stage B tile [128, K] ----
    {
        const bf16* wh = WHbase + J.woff;
        const bf16* wl = WLbase + J.woff;
        const int c8n = K >> 3;
        for (int idx = t; idx < 128*c8n; idx += 256) {
            const int row = idx / c8n, c8 = idx - row*c8n;
            *(uint4*)&Bh[row*KP + c8*8] = ((const uint4*)(wh + (size_t)row*K))[c8];
            *(uint4*)&Bl[row*KP + c8*8] = ((const uint4*)(wl + (size_t)row*K))[c8];
        }
    }
    __syncthreads();

    const int wid = t >> 5, lane = t & 31;
    const int wm = wid & 1, wn = wid >> 1;     // 2 (M) x 4 (N) warps
    const int gID = lane >> 2, tig = lane & 3;

    const uint32_t laneOff = (uint32_t)(((lane & 15)*KP + (lane >> 4)*8) * 2);
    const uint32_t aHiB = (uint32_t)__cvta_generic_to_shared(Ah) + (uint32_t)(wm*32*KP*2) + laneOff;
    const uint32_t aLoB = (uint32_t)__cvta_generic_to_shared(Al) + (uint32_t)(wm*32*KP*2) + laneOff;
    const uint32_t bHiB = (uint32_t)__cvta_generic_to_shared(Bh) + (uint32_t)(wn*32*KP*2) + laneOff;
    const uint32_t bLoB = (uint32_t)__cvta_generic_to_shared(Bl) + (uint32_t)(wn*32*KP*2) + laneOff;
    const uint32_t mtOff = (uint32_t)(16*KP*2);

    float acc[2][4][4];
#pragma unroll
    for (int mt = 0; mt < 2; mt++)
#pragma unroll
        for (int nt = 0; nt < 4; nt++)
#pragma unroll
            for (int q = 0; q < 4; q++) acc[mt][nt][q] = 0.f;

    // F[0..1]=Ah mt0/mt1, F[2..3]=Al, F[4..5]=Bh lo/hi-16rows, F[6..7]=Bl
#define LOAD_FRAGS(F, ko) do { \
        LDSM4((F)[0], aHiB + (ko)); \
        LDSM4((F)[1], aHiB + mtOff + (ko)); \
        LDSM4((F)[2], aLoB + (ko)); \
        LDSM4((F)[3], aLoB + mtOff + (ko)); \
        LDSM4((F)[4], bHiB + (ko)); \
        LDSM4((F)[5], bHiB + mtOff + (ko)); \
        LDSM4((F)[6], bLoB + (ko)); \
        LDSM4((F)[7], bLoB + mtOff + (ko)); \
    } while (0)

#define DO_MMAS(F) do { \
        _Pragma("unroll") \
        for (int mt = 0; mt < 2; mt++) { \
            const uint32_t* ahh = (F)[mt]; \
            const uint32_t* all = (F)[2 + mt]; \
            mma16816(acc[mt][0], ahh, (F)[4][0], (F)[4][2]); \
            mma16816(acc[mt][0], ahh, (F)[6][0], (F)[6][2]); \
            mma16816(acc[mt][0], all, (F)[4][0], (F)[4][2]); \
            mma16816(acc[mt][1], ahh, (F)[4][1], (F)[4][3]); \
            mma16816(acc[mt][1], ahh, (F)[6][1], (F)[6][3]); \
            mma16816(acc[mt][1], all, (F)[4][1], (F)[4][3]); \
            mma16816(acc[mt][2], ahh, (F)[5][0], (F)[5][2]); \
            mma16816(acc[mt][2], ahh, (F)[7][0], (F)[7][2]); \
            mma16816(acc[mt][2], all, (F)[5][0], (F)[5][2]); \
            mma16816(acc[mt][3], ahh, (F)[5][1], (F)[5][3]); \
            mma16816(acc[mt][3], ahh, (F)[7][1], (F)[7][3]); \
            mma16816(acc[mt][3], all, (F)[5][1], (F)[5][3]); \
        } \
    } while (0)

    const int KS = K >> 4;     // always even (2 or 8)
    uint32_t F0[8][4], F1[8][4];
    LOAD_FRAGS(F0, 0u);
#pragma unroll 1
    for (int ks = 0; ks < KS; ks += 2) {
        LOAD_FRAGS(F1, (uint32_t)((ks + 1) * 32));
        DO_MMAS(F0);
        if (ks + 2 < KS) LOAD_FRAGS(F0, (uint32_t)((ks + 2) * 32));
        DO_MMAS(F1);
    }

    // ---- epilogue ----
#pragma unroll
    for (int mt = 0; mt < 2; mt++) {
        const int row = m0 + wm*32 + mt*16 + gID;
#pragma unroll
        for (int nt = 0; nt < 4; nt++) {
            const int cl = wn*32 + nt*8 + 2*tig;
            float2 v0 = make_float2(acc[mt][nt][0], acc[mt][nt][1]);
            float2 v1 = make_float2(acc[mt][nt][2], acc[mt][nt][3]);
            if (J.bias) {
                const float2 bb = *(const float2*)&J.bias[cl];
                v0.x += bb.x; v0.y += bb.y;
                v1.x += bb.x; v1.y += bb.y;
            }
            const int col = J.col0 + cl;
            if (J.Cf) {
                *(float2*)&J.Cf[(size_t)row*J.cstride + col]       = v0;
                *(float2*)&J.Cf[(size_t)(row + 8)*J.cstride + col] = v1;
            } else {
                const bf16 h0x = __float2bfloat16(v0.x), h0y = __float2bfloat16(v0.y);
                const bf16 h1x = __float2bfloat16(v1.x), h1y = __float2bfloat16(v1.y);
                bf162 h0; h0.x = h0x; h0.y = h0y;
                bf162 h1; h1.x = h1x; h1.y = h1y;
                bf162 l0; l0.x = __float2bfloat16(v0.x - __bfloat162float(h0x));
                          l0.y = __float2bfloat16(v0.y - __bfloat162float(h0y));
                bf162 l1; l1.x = __float2bfloat16(v1.x - __bfloat162float(h1x));
                          l1.y = __float2bfloat16(v1.y - __bfloat162float(h1y));
                *(bf162*)&J.Chi[(size_t)row*J.cstride + col]       = h0;
                *(bf162*)&J.Chi[(size_t)(row + 8)*J.cstride + col] = h1;
                *(bf162*)&J.Clo[(size_t)row*J.cstride + col]       = l0;
                *(bf162*)&J.Clo[(size_t)(row + 8)*J.cstride + col] = l1;
            }
        }
    }
#undef LOAD_FRAGS
#undef DO_MMAS
}

// ============================================================================
// Fused edge kernel, both directions; residual + output in split bf16.
// ============================================================================
extern "C" __global__ void __launch_bounds__(256)
edge2_kernel(const float* __restrict__ XLa, const float* __restrict__ XRa,
             const float* __restrict__ XLb, const float* __restrict__ XRb,
             const float* __restrict__ attA, const float* __restrict__ attB,
             const float* __restrict__ biasA, const float* __restrict__ biasB,
             const float* __restrict__ FDa, const float* __restrict__ FSa,
             const float* __restrict__ FDb, const float* __restrict__ FSb,
             const bf16* __restrict__ XdAh, const bf16* __restrict__ XdAl,
             const bf16* __restrict__ XdBh, const bf16* __restrict__ XdBl,
             bf16* __restrict__ OUTah, bf16* __restrict__ OUTal,
             bf16* __restrict__ OUTbh, bf16* __restrict__ OUTbl)
{
    extern __shared__ float sm[];
    float* sXL  = sm;            // 5120
    float* sXR  = sm + 5120;
    float* sFd  = sm + 10240;    // 1280
    float* sFs  = sm + 11520;
    float* sSd  = sm + 12800;
    float* sSs  = sm + 14080;
    float* sXd  = sm + 15360;    // 1280
    float* sLog = sm + 16640;    // 640
    float* sAtt = sm + 17280;    // 512

    const int dir = blockIdx.x >> 11;
    const int g = blockIdx.x & 2047;
    const int t = threadIdx.x;
    const int wid = t >> 5, lane = t & 31;

    const float* XL   = dir ? XLb : XLa;
    const float* XR   = dir ? XRb : XRa;
    const float* att  = dir ? attB : attA;
    const float* gbias= dir ? biasB : biasA;
    const float* FDSD = dir ? FDb : FDa;
    const float* FSSS = dir ? FSb : FSa;
    const bf16* Xdh   = dir ? XdBh : XdAh;
    const bf16* Xdl   = dir ? XdBl : XdAl;
    bf16* OUTh        = dir ? OUTbh : OUTah;
    bf16* OUTl        = dir ? OUTbl : OUTal;

    const size_t base = (size_t)g * 5120;
    for (int idx = t; idx < 5120; idx += 256) {
        sXL[idx] = XL[base + idx];
        sXR[idx] = XR[base + idx];
    }
    for (int idx = t; idx < 1280; idx += 256) {
        const int i = idx >> 7, c = idx & 127;
        const size_t b2 = (size_t)(g*10 + i)*256 + c;
        const size_t bx = (size_t)(g*10 + i)*128 + c;
        sFd[idx] = FDSD[b2];  sSd[idx] = FDSD[b2 + 128];
        sFs[idx] = FSSS[b2];  sSs[idx] = FSSS[b2 + 128];
        sXd[idx] = __bfloat162float(Xdh[bx]) + __bfloat162float(Xdl[bx]);
    }
    for (int idx = t; idx < 512; idx += 256) sAtt[idx] = att[idx];
    __syncthreads();

#pragma unroll 1
    for (int pp = 0; pp < 5; pp++) {
        const int p = wid + pp * 8;
        const int h = p / 10, j = p % 10;
        const float4 xr = *(const float4*)&sXR[j*512 + h*128 + lane*4];
        const float4 at = *(const float4*)&sAtt[h*128 + lane*4];
#pragma unroll
        for (int i = 0; i < 10; i++) {
            const float4 xl = *(const float4*)&sXL[i*512 + h*128 + lane*4];
            float e, sv;
            e = xl.x + xr.x; sv = at.x * fmaf(e, 0.6f, 0.4f*fabsf(e));
            e = xl.y + xr.y; sv = fmaf(at.y, fmaf(e, 0.6f, 0.4f*fabsf(e)), sv);
            e = xl.z + xr.z; sv = fmaf(at.z, fmaf(e, 0.6f, 0.4f*fabsf(e)), sv);
            e = xl.w + xr.w; sv = fmaf(at.w, fmaf(e, 0.6f, 0.4f*fabsf(e)), sv);
#pragma unroll
            for (int o = 16; o > 0; o >>= 1) sv += __shfl_xor_sync(0xffffffffu, sv, o);
            if (lane == 0) sLog[p*16 + i] = sv;
        }
    }
    __syncthreads();

    if (t < 40) {
        float* lg = sLog + t*16;
        float m = lg[0];
#pragma unroll
        for (int i = 1; i < 10; i++) m = fmaxf(m, lg[i]);
        float a[10]; float sum = 0.f;
#pragma unroll
        for (int i = 0; i < 10; i++) { a[i] = __expf(lg[i] - m); sum += a[i]; }
        const float inv = __fdividef(1.f, sum);
#pragma unroll
        for (int i = 0; i < 10; i++) lg[i] = a[i] * inv;
    }
    __syncthreads();

    {
        const int c = t & 127, rh = t >> 7;
        float accj[5] = {0.f, 0.f, 0.f, 0.f, 0.f};
#pragma unroll
        for (int h = 0; h < 4; h++) {
            float xlh[10];
#pragma unroll
            for (int i = 0; i < 10; i++) xlh[i] = sXL[i*512 + h*128 + c];
#pragma unroll
            for (int jj = 0; jj < 5; jj++) {
                const float* al = sLog + (h*10 + rh*5 + jj)*16;
                float v = accj[jj];
#pragma unroll
                for (int i = 0; i < 10; i++) v = fmaf(al[i], xlh[i], v);
                accj[jj] = v;
            }
        }
        const float bv = gbias[c];
#pragma unroll
        for (int jj = 0; jj < 5; jj++) {
            const int i = rh*5 + jj;
            const float fd = sFd[i*128 + c];
            const float sd = sSd[i*128 + c];
            float cg = sXd[i*128 + c];
#pragma unroll
            for (int j = 0; j < 10; j++) {
                const float f = fd + sFs[j*128 + c];
                const float s2 = sd + sSs[j*128 + c];
                const float sig = __fdividef(1.f, 1.f + __expf(-f));
                const float sp  = fmaxf(s2, 0.f) + __logf(1.f + __expf(-fabsf(s2)));
                cg = fmaf(sig, sp, cg);
            }
            const float v = accj[jj]*0.25f + bv + cg;
            const size_t idx = (size_t)(g*10 + i)*128 + c;
            const bf16 h = __float2bfloat16(v);
            OUTh[idx] = h;
            OUTl[idx] = __float2bfloat16(v - __bfloat162float(h));
        }
    }
}

// ============================================================================
// Head: split-bf16 inputs
// ============================================================================
extern "C" __global__ void __launch_bounds__(128)
head_kernel(const bf16* __restrict__ XMh, const bf16* __restrict__ XMl,
            const bf16* __restrict__ XOh, const bf16* __restrict__ XOl,
            const float* __restrict__ W1, const float* __restrict__ b1,
            const float* __restrict__ W2, const float* __restrict__ b2,
            float* __restrict__ out)
{
    __shared__ float pool[256], red[128];
    const int g = blockIdx.x, t = threadIdx.x;
    {
        float pm = 0.f, po = 0.f;
#pragma unroll
        for (int r = 0; r < 10; r++) {
            const size_t idx = (size_t)(g*10 + r)*128 + t;
            pm += __bfloat162float(XMh[idx]) + __bfloat162float(XMl[idx]);
            po += __bfloat162float(XOh[idx]) + __bfloat162float(XOl[idx]);
        }
        pool[t] = pm * 0.1f;
        pool[128 + t] = po * 0.1f;
    }
    __syncthreads();
    {
        float a = 0.f;
#pragma unroll 4
        for (int k = 0; k < 256; k++) a = fmaf(pool[k], W1[k*128 + t], a);
        a += b1[t];
        a = (a >= 0.f) ? a : 128.f * a;
        red[t] = a * W2[t];
    }
    __syncthreads();
    if (t < 32) {
        float v = red[t] + red[t+32] + red[t+64] + red[t+96];
#pragma unroll
        for (int o = 16; o > 0; o >>= 1) v += __shfl_xor_sync(0xffffffffu, v, o);
        if (t == 0) out[g] = v + b2[0];
    }
}

// ============================================================================
// Host launcher
// ============================================================================
extern "C" void kernel_launch(void* const* d_in, const int* in_sizes, int n_in,
                              void* d_out, int out_size)
{
    const float* x_my   = (const float*)d_in[0];
    const float* x_opp  = (const float*)d_in[1];
    const float* W_enc  = (const float*)d_in[2];
    const float* b_enc  = (const float*)d_in[3];
    const float* gb_Wl  = (const float*)d_in[4];
    const float* gb_Wr  = (const float*)d_in[5];
    const float* gb_att = (const float*)d_in[6];
    const float* gb_b   = (const float*)d_in[7];
    const float* gr_Wl  = (const float*)d_in[8];
    const float* gr_Wr  = (const float*)d_in[9];
    const float* gr_att = (const float*)d_in[10];
    const float* gr_b   = (const float*)d_in[11];
    const float* cl_Wf  = (const float*)d_in[12];
    const float* cl_bf  = (const float*)d_in[13];
    const float* cl_Ws  = (const float*)d_in[14];
    const float* cl_bs  = (const float*)d_in[15];
    const float* cr_Wf  = (const float*)d_in[16];
    const float* cr_bf  = (const float*)d_in[17];
    const float* cr_Ws  = (const float*)d_in[18];
    const float* cr_bs  = (const float*)d_in[19];
    const float* node_W = (const float*)d_in[20];
    const float* node_b = (const float*)d_in[21];
    const float* W1     = (const float*)d_in[22];
    const float* b1     = (const float*)d_in[23];
    const float* W2     = (const float*)d_in[24];
    const float* b2     = (const float*)d_in[25];

    bf16 *XMh, *XMl, *XOh, *XOl, *NMh, *NMl, *NOh, *NOl, *XAh, *XAl, *WH, *WL;
    float *XL, *XR, *XL2, *XR2, *FDSD, *FSSS, *FDSD2, *FSSS2;
    cudaGetSymbolAddress((void**)&XMh, g_XMh);  cudaGetSymbolAddress((void**)&XMl, g_XMl);
    cudaGetSymbolAddress((void**)&XOh, g_XOh);  cudaGetSymbolAddress((void**)&XOl, g_XOl);
    cudaGetSymbolAddress((void**)&NMh, g_NMh);  cudaGetSymbolAddress((void**)&NMl, g_NMl);
    cudaGetSymbolAddress((void**)&NOh, g_NOh);  cudaGetSymbolAddress((void**)&NOl, g_NOl);
    cudaGetSymbolAddress((void**)&XAh, g_XAh);  cudaGetSymbolAddress((void**)&XAl, g_XAl);
    cudaGetSymbolAddress((void**)&XL, g_XL);    cudaGetSymbolAddress((void**)&XR, g_XR);
    cudaGetSymbolAddress((void**)&XL2, g_XL2);  cudaGetSymbolAddress((void**)&XR2, g_XR2);
    cudaGetSymbolAddress((void**)&FDSD, g_FDSD);   cudaGetSymbolAddress((void**)&FSSS, g_FSSS);
    cudaGetSymbolAddress((void**)&FDSD2, g_FDSD2); cudaGetSymbolAddress((void**)&FSSS2, g_FSSS2);
    cudaGetSymbolAddress((void**)&WH, g_Whi);   cudaGetSymbolAddress((void**)&WL, g_Wlo);

    const int gemmSmemMax = (2*64 + 2*128) * (Hd + 8) * 2;   // 104448
    cudaFuncSetAttribute(gemm_batch_kernel,
                         cudaFuncAttributeMaxDynamicSharedMemorySize, gemmSmemMax);
    const int edgeSmem = 17792 * 4;
    cudaFuncSetAttribute(edge2_kernel,
                         cudaFuncAttributeMaxDynamicSharedMemorySize, edgeSmem);

    // ---- prep ----
    prep_gat<<<32, 256>>>(gb_Wl, gb_Wr, gr_Wl, gr_Wr, WH, WL);
    prep_cg<<<16, 256>>>(cl_Wf, cl_Ws, cr_Wf, cr_Ws, WH, WL);
    prep_misc<<<43, 256>>>(W_enc, node_W, x_my, x_opp, WH, WL, XAh, XAl);

    const int MT = NNODE / 64;   // 320 m-tiles

    auto launch_batch = [&](const JobBatch& jb, int njobs, int K) {
        const int smem = (2*64 + 2*128) * (K + 8) * 2;
        dim3 grid(MT, njobs);
        gemm_batch_kernel<<<grid, 256, smem>>>(jb, WH, WL, K);
    };

    // ---- encoder batch (K=32, 2 jobs, split-bf16 out) ----
    {
        JobBatch jb{};
        jb.j[0] = { XAh,              XAl,              0, b_enc, nullptr, XMh, XMl, Hd, 0 };
        jb.j[1] = { XAh + NNODE*CDm,  XAl + NNODE*CDm,  0, b_enc, nullptr, XOh, XOl, Hd, 0 };
        launch_batch(jb, 2, CDm);
    }

    for (int l = 0; l < 2; l++) {
        const long long L = (long long)LOFF(l);
        const long long WLB = L, WRB = L + 4*(long long)TSZ;
        const long long WLR = L + 8*(long long)TSZ, WRR = L + 12*(long long)TSZ;
        const long long CLD = L + 16*(long long)TSZ, CLS = L + 18*(long long)TSZ;
        const long long CRD = L + 20*(long long)TSZ, CRS = L + 22*(long long)TSZ;
        const long long NW  = L + 24*(long long)TSZ;
        const float* att_b = gb_att + l*4*Hd;
        const float* att_r = gr_att + l*4*Hd;
        const float* bb = gb_b + l*Hd;
        const float* br = gr_b + l*Hd;
        const float* clbf = cl_bf + l*Hd;  const float* clbs = cl_bs + l*Hd;
        const float* crbf = cr_bf + l*Hd;  const float* crbs = cr_bs + l*Hd;
        const float* nb = node_b + l*Hd;

        // ---- phase GEMM batch: 24 jobs, both directions, fp32 outputs ----
        {
            JobBatch jb{};
            int n = 0;
            for (int tile = 0; tile < 4; tile++)
                jb.j[n++] = { XMh, XMl, WLB + tile*(long long)TSZ, nullptr, XL, nullptr, nullptr, 512, tile*128 };
            for (int tile = 0; tile < 4; tile++)
                jb.j[n++] = { XOh, XOl, WRB + tile*(long long)TSZ, nullptr, XR, nullptr, nullptr, 512, tile*128 };
            jb.j[n++] = { XOh, XOl, CLD,                  clbf,    FDSD, nullptr, nullptr, 256, 0   };
            jb.j[n++] = { XOh, XOl, CLD + (long long)TSZ, clbs,    FDSD, nullptr, nullptr, 256, 128 };
            jb.j[n++] = { XMh, XMl, CLS,                  nullptr, FSSS, nullptr, nullptr, 256, 0   };
            jb.j[n++] = { XMh, XMl, CLS + (long long)TSZ, nullptr, FSSS, nullptr, nullptr, 256, 128 };
            for (int tile = 0; tile < 4; tile++)
                jb.j[n++] = { XOh, XOl, WLR + tile*(long long)TSZ, nullptr, XL2, nullptr, nullptr, 512, tile*128 };
            for (int tile = 0; tile < 4; tile++)
                jb.j[n++] = { XMh, XMl, WRR + tile*(long long)TSZ, nullptr, XR2, nullptr, nullptr, 512, tile*128 };
            jb.j[n++] = { XMh, XMl, CRD,                  crbf,    FDSD2, nullptr, nullptr, 256, 0   };
            jb.j[n++] = { XMh, XMl, CRD + (long long)TSZ, crbs,    FDSD2, nullptr, nullptr, 256, 128 };
            jb.j[n++] = { XOh, XOl, CRS,                  nullptr, FSSS2, nullptr, nullptr, 256, 0   };
            jb.j[n++] = { XOh, XOl, CRS + (long long)TSZ, nullptr, FSSS2, nullptr, nullptr, 256, 128 };
            launch_batch(jb, 24, Hd);
        }

        // ---- edges, both directions; split-bf16 residual in / out ----
        edge2_kernel<<<2*NG, 256, edgeSmem>>>(
            XL, XR, XL2, XR2, att_b, att_r, bb, br,
            FDSD, FSSS, FDSD2, FSSS2,
            XOh, XOl, XMh, XMl,
            NOh, NOl, NMh, NMl);

        // ---- node linear batch (2 jobs, split-bf16 out) ----
        {
            JobBatch jb{};
            jb.j[0] = { NMh, NMl, NW, nb, nullptr, XMh, XMl, Hd, 0 };
            jb.j[1] = { NOh, NOl, NW, nb, nullptr, XOh, XOl, Hd, 0 };
            launch_batch(jb, 2, Hd);
        }
    }

    head_kernel<<<NG, 128>>>(XMh, XMl, XOh, XOl, W1, b1, W2, b2, (float*)d_out);
}